// round 2
// baseline (speedup 1.0000x reference)
#include <cuda_runtime.h>
#include <cstdint>
#include <cstddef>

// ---------------------------------------------------------------------------
// Dual cross-attention (e2s, s2e), tf32 mma.sync, fragment-packed SMEM layout.
// Packed unit (16B) = the 4 tf32 words lane (g,tg) consumes for k-steps
// (2*kk2, 2*kk2+1):  {X[r][2kk2*8+tg], X[r][..+4], X[r][(2kk2+1)*8+tg], ..+4}
// unit index u = tg*2 + (kk2&1) + (kk2>>1)*8   (64-col tiles, stride 68 words)
//            u = tg*2 + kk2                    (32-col tiles, stride 36 words)
// Bank-group = (r + u) % 8 -> distinct across every 8-lane LDS.128 phase.
// ---------------------------------------------------------------------------

constexpr int kB = 4;
constexpr int kT = 2048;
constexpr int kD = 512;
constexpr int kH = 8;
constexpr int kDK = 64;
constexpr int kM = kB * kT;  // 8192 rows
constexpr float kSmScale = 1.5f / 8.0f;  // SCALE / sqrt(DK)
constexpr float kLog2e = 1.4426950408889634f;

__device__ float g_Q[(size_t)kM * kD];
__device__ float g_K[(size_t)kM * kD];
__device__ float g_V[(size_t)kM * kD];
__device__ float g_O[(size_t)kM * kD];

__device__ __forceinline__ uint32_t f2tf(float f) {
  uint32_t u;
  asm("cvt.rna.tf32.f32 %0, %1;" : "=r"(u) : "f"(f));
  return u;
}

__device__ __forceinline__ void st64(uint32_t* p, uint32_t a, uint32_t b) {
  *reinterpret_cast<uint2*>(p) = make_uint2(a, b);
}

// D += A(16x8, row) * B(8x8, col), tf32 in, fp32 accum.
__device__ __forceinline__ void mma8(float* d, const uint32_t* a, uint32_t b0,
                                     uint32_t b1) {
  asm volatile(
      "mma.sync.aligned.m16n8k8.row.col.f32.tf32.tf32.f32 "
      "{%0,%1,%2,%3}, {%4,%5,%6,%7}, {%8,%9}, {%0,%1,%2,%3};\n"
      : "+f"(d[0]), "+f"(d[1]), "+f"(d[2]), "+f"(d[3])
      : "r"(a[0]), "r"(a[1]), "r"(a[2]), "r"(a[3]), "r"(b0), "r"(b1));
}

// ---------------------------------------------------------------------------
// C[8192,512] = A[8192,512] @ W[512,512]^T. CTA 128x128, k-tile 32,
// 8 warps = 4(M) x 2(N). Packed-fragment SMEM (stride 36 words).
// ---------------------------------------------------------------------------
__global__ void __launch_bounds__(256, 2)
    gemm_nt_tf32(const float* __restrict__ A, const float* __restrict__ W,
                 float* __restrict__ C) {
  __shared__ uint32_t sA[128 * 36];
  __shared__ uint32_t sB[128 * 36];

  const int tid = threadIdx.x;
  const int lane = tid & 31;
  const int wid = tid >> 5;
  const int wm = wid & 3;
  const int wn = wid >> 2;
  const int g = lane >> 2;
  const int tg = lane & 3;
  const int m0 = blockIdx.x * 128;
  const int n0 = blockIdx.y * 128;

  float acc[2][8][4];
#pragma unroll
  for (int mi = 0; mi < 2; ++mi)
#pragma unroll
    for (int ni = 0; ni < 8; ++ni)
#pragma unroll
      for (int c = 0; c < 4; ++c) acc[mi][ni][c] = 0.f;

  for (int k0 = 0; k0 < kD; k0 += 32) {
    __syncthreads();
    // ---- stage: 512 octet-tasks (row r, octet oc of 4), 2 per thread/tile --
#pragma unroll
    for (int it = 0; it < 2; ++it) {
      int task = it * 256 + tid;
      int r = task >> 2;
      int oc = task & 3;
      const float* pa = A + (size_t)(m0 + r) * kD + k0 + oc * 8;
      float4 alo = *reinterpret_cast<const float4*>(pa);
      float4 ahi = *reinterpret_cast<const float4*>(pa + 4);
      const float* pb = W + (size_t)(n0 + r) * kD + k0 + oc * 8;
      float4 blo = *reinterpret_cast<const float4*>(pb);
      float4 bhi = *reinterpret_cast<const float4*>(pb + 4);
      int kk2 = oc >> 1;
      int jlo = (oc & 1) << 1;
      int base = r * 36 + jlo;
      st64(sA + base + (0 * 2 + kk2) * 4, f2tf(alo.x), f2tf(ahi.x));
      st64(sA + base + (1 * 2 + kk2) * 4, f2tf(alo.y), f2tf(ahi.y));
      st64(sA + base + (2 * 2 + kk2) * 4, f2tf(alo.z), f2tf(ahi.z));
      st64(sA + base + (3 * 2 + kk2) * 4, f2tf(alo.w), f2tf(ahi.w));
      st64(sB + base + (0 * 2 + kk2) * 4, f2tf(blo.x), f2tf(bhi.x));
      st64(sB + base + (1 * 2 + kk2) * 4, f2tf(blo.y), f2tf(bhi.y));
      st64(sB + base + (2 * 2 + kk2) * 4, f2tf(blo.z), f2tf(bhi.z));
      st64(sB + base + (3 * 2 + kk2) * 4, f2tf(blo.w), f2tf(bhi.w));
    }
    __syncthreads();

#pragma unroll
    for (int kk2 = 0; kk2 < 2; ++kk2) {
      const int u4 = (tg * 2 + kk2) * 4;
      uint32_t ae[2][4], ao[2][4];
#pragma unroll
      for (int mi = 0; mi < 2; ++mi) {
        int rb = wm * 32 + mi * 16;
        uint4 v0 = *reinterpret_cast<const uint4*>(sA + (rb + g) * 36 + u4);
        uint4 v1 = *reinterpret_cast<const uint4*>(sA + (rb + g + 8) * 36 + u4);
        ae[mi][0] = v0.x; ae[mi][1] = v1.x; ae[mi][2] = v0.y; ae[mi][3] = v1.y;
        ao[mi][0] = v0.z; ao[mi][1] = v1.z; ao[mi][2] = v0.w; ao[mi][3] = v1.w;
      }
#pragma unroll
      for (int ni = 0; ni < 8; ++ni) {
        uint4 vb = *reinterpret_cast<const uint4*>(
            sB + (wn * 64 + ni * 8 + g) * 36 + u4);
        mma8(acc[0][ni], ae[0], vb.x, vb.y);
        mma8(acc[0][ni], ao[0], vb.z, vb.w);
        mma8(acc[1][ni], ae[1], vb.x, vb.y);
        mma8(acc[1][ni], ao[1], vb.z, vb.w);
      }
    }
  }

#pragma unroll
  for (int mi = 0; mi < 2; ++mi) {
    int row = m0 + wm * 32 + mi * 16 + g;
#pragma unroll
    for (int ni = 0; ni < 8; ++ni) {
      int col = n0 + wn * 64 + ni * 8 + 2 * tg;
      float2 v0 = make_float2(acc[mi][ni][0], acc[mi][ni][1]);
      float2 v1 = make_float2(acc[mi][ni][2], acc[mi][ni][3]);
      *reinterpret_cast<float2*>(C + (size_t)row * kD + col) = v0;
      *reinterpret_cast<float2*>(C + (size_t)(row + 8) * kD + col) = v1;
    }
  }
}

// ---------------------------------------------------------------------------
// Flash attention: CTA = (64-query tile, head, batch), 4 warps x 16 rows.
// Packed-fragment SMEM (stride 68 words). V staged pre-transposed.
// P tile reuses sK (warp-private rows) after a CTA sync.
// ---------------------------------------------------------------------------
__global__ void __launch_bounds__(128)
    attn_tf32(const float* __restrict__ Qg, const float* __restrict__ Kg,
              const float* __restrict__ Vg, const int* __restrict__ mask,
              float* __restrict__ Og) {
  __shared__ uint32_t sK[64 * 68];  // K packed; reused as Q stage + P tile
  __shared__ uint32_t sV[64 * 68];  // V^T packed
  __shared__ float sBias[64];

  const int tid = threadIdx.x;
  const int lane = tid & 31;
  const int w = tid >> 5;
  const int g = lane >> 2;
  const int tg = lane & 3;
  const int bb = blockIdx.z;
  const int h = blockIdx.y;
  const int q0 = blockIdx.x * 64;
  const int colh = h * kDK;
  const size_t qrow0 = (size_t)bb * kT + q0;
  const size_t kvrow0 = (size_t)bb * kT;
  const int w16 = w * 16;

  // ---- stage Q (packed, into sK), lift to register A-fragments ----
#pragma unroll
  for (int it = 0; it < 4; ++it) {
    int task = it * 128 + tid;
    int r = task >> 3;
    int oc = task & 7;
    const float* p = Qg + (qrow0 + r) * kD + colh + oc * 8;
    float4 lo = *reinterpret_cast<const float4*>(p);
    float4 hi = *reinterpret_cast<const float4*>(p + 4);
    int kk2 = oc >> 1;
    int ub = (kk2 & 1) + ((kk2 >> 1) << 3);
    int base = r * 68 + ((oc & 1) << 1);
    st64(sK + base + (0 * 2 + ub) * 4, f2tf(lo.x), f2tf(hi.x));
    st64(sK + base + (1 * 2 + ub) * 4, f2tf(lo.y), f2tf(hi.y));
    st64(sK + base + (2 * 2 + ub) * 4, f2tf(lo.z), f2tf(hi.z));
    st64(sK + base + (3 * 2 + ub) * 4, f2tf(lo.w), f2tf(hi.w));
  }
  __syncthreads();

  uint32_t aq[8][4];
#pragma unroll
  for (int kk2 = 0; kk2 < 4; ++kk2) {
    int u4 = (tg * 2 + (kk2 & 1) + ((kk2 >> 1) << 3)) * 4;
    uint4 v0 = *reinterpret_cast<const uint4*>(sK + (w16 + g) * 68 + u4);
    uint4 v1 = *reinterpret_cast<const uint4*>(sK + (w16 + g + 8) * 68 + u4);
    aq[2 * kk2][0] = v0.x; aq[2 * kk2][1] = v1.x;
    aq[2 * kk2][2] = v0.y; aq[2 * kk2][3] = v1.y;
    aq[2 * kk2 + 1][0] = v0.z; aq[2 * kk2 + 1][1] = v1.z;
    aq[2 * kk2 + 1][2] = v0.w; aq[2 * kk2 + 1][3] = v1.w;
  }

  float o[8][4];
#pragma unroll
  for (int ni = 0; ni < 8; ++ni)
#pragma unroll
    for (int c = 0; c < 4; ++c) o[ni][c] = 0.f;
  float mrow0 = -INFINITY, mrow1 = -INFINITY;
  float l0 = 0.f, l1 = 0.f;
  const float sc = kSmScale * kLog2e;

  for (int j0 = 0; j0 < kT; j0 += 64) {
    __syncthreads();  // prior chunk's reads of sK/sV complete

    // ---- stage K (packed rows = key, cols = dim) ----
#pragma unroll
    for (int it = 0; it < 4; ++it) {
      int task = it * 128 + tid;
      int r = task >> 3;
      int oc = task & 7;
      const float* p = Kg + (kvrow0 + j0 + r) * kD + colh + oc * 8;
      float4 lo = *reinterpret_cast<const float4*>(p);
      float4 hi = *reinterpret_cast<const float4*>(p + 4);
      int kk2 = oc >> 1;
      int ub = (kk2 & 1) + ((kk2 >> 1) << 3);
      int base = r * 68 + ((oc & 1) << 1);
      st64(sK + base + (0 * 2 + ub) * 4, f2tf(lo.x), f2tf(hi.x));
      st64(sK + base + (1 * 2 + ub) * 4, f2tf(lo.y), f2tf(hi.y));
      st64(sK + base + (2 * 2 + ub) * 4, f2tf(lo.z), f2tf(hi.z));
      st64(sK + base + (3 * 2 + ub) * 4, f2tf(lo.w), f2tf(hi.w));
    }
    // ---- stage V^T (packed rows = dim, cols = key; key pairs j,j+4) ----
#pragma unroll
    for (int it = 0; it < 4; ++it) {
      int task = it * 128 + tid;
      int jj_idx = task >> 4;                            // 0..31
      int dq = task & 15;                                // dim quad
      int jj = ((jj_idx >> 2) << 3) + (jj_idx & 3);      // key, bit2 == 0
      const float* p = Vg + (kvrow0 + j0 + jj) * kD + colh + dq * 4;
      float4 lo = *reinterpret_cast<const float4*>(p);
      float4 hi = *reinterpret_cast<const float4*>(p + 4 * kD);  // key jj+4
      int kk = jj >> 3;
      int u = ((jj & 3) << 1) + ((kk >> 1) & 1) + ((kk >> 2) << 3);
      int base = u * 4 + ((kk & 1) << 1);
      st64(sV + (dq * 4 + 0) * 68 + base, f2tf(lo.x), f2tf(hi.x));
      st64(sV + (dq * 4 + 1) * 68 + base, f2tf(lo.y), f2tf(hi.y));
      st64(sV + (dq * 4 + 2) * 68 + base, f2tf(lo.z), f2tf(hi.z));
      st64(sV + (dq * 4 + 3) * 68 + base, f2tf(lo.w), f2tf(hi.w));
    }
    if (tid < 64)
      sBias[tid] = mask[kvrow0 + j0 + tid] ? 0.f : -1.4426950e30f;
    __syncthreads();

    // ---- S = Q K^T ----
    float s[8][4];
#pragma unroll
    for (int ni = 0; ni < 8; ++ni)
#pragma unroll
      for (int c = 0; c < 4; ++c) s[ni][c] = 0.f;
#pragma unroll
    for (int kk2 = 0; kk2 < 4; ++kk2) {
      int u4 = (tg * 2 + (kk2 & 1) + ((kk2 >> 1) << 3)) * 4;
#pragma unroll
      for (int ni = 0; ni < 8; ++ni) {
        uint4 vb = *reinterpret_cast<const uint4*>(
            sK + (ni * 8 + g) * 68 + u4);
        mma8(s[ni], aq[2 * kk2], vb.x, vb.y);
        mma8(s[ni], aq[2 * kk2 + 1], vb.z, vb.w);
      }
    }

    // ---- scale + mask bias, row max ----
    float mx0 = -INFINITY, mx1 = -INFINITY;
#pragma unroll
    for (int ni = 0; ni < 8; ++ni) {
      float bb0 = sBias[ni * 8 + 2 * tg];
      float bb1 = sBias[ni * 8 + 2 * tg + 1];
      s[ni][0] = s[ni][0] * sc + bb0;
      s[ni][1] = s[ni][1] * sc + bb1;
      s[ni][2] = s[ni][2] * sc + bb0;
      s[ni][3] = s[ni][3] * sc + bb1;
      mx0 = fmaxf(mx0, fmaxf(s[ni][0], s[ni][1]));
      mx1 = fmaxf(mx1, fmaxf(s[ni][2], s[ni][3]));
    }
    mx0 = fmaxf(mx0, __shfl_xor_sync(0xffffffffu, mx0, 1));
    mx0 = fmaxf(mx0, __shfl_xor_sync(0xffffffffu, mx0, 2));
    mx1 = fmaxf(mx1, __shfl_xor_sync(0xffffffffu, mx1, 1));
    mx1 = fmaxf(mx1, __shfl_xor_sync(0xffffffffu, mx1, 2));
    float mn0 = fmaxf(mrow0, mx0);
    float mn1 = fmaxf(mrow1, mx1);
    float al0 = exp2f(mrow0 - mn0);
    float al1 = exp2f(mrow1 - mn1);
    mrow0 = mn0;
    mrow1 = mn1;

    __syncthreads();  // all warps done reading sK -> reuse as packed P

    // ---- exp2, write P (packed, warp-private rows) ----
    const int tlow = tg & 1, thi = tg >> 1;
    float rs0 = 0.f, rs1 = 0.f;
#pragma unroll
    for (int ni = 0; ni < 8; ++ni) {
      float p0 = exp2f(s[ni][0] - mn0);
      float p1 = exp2f(s[ni][1] - mn0);
      float p2 = exp2f(s[ni][2] - mn1);
      float p3 = exp2f(s[ni][3] - mn1);
      rs0 += p0 + p1;
      rs1 += p2 + p3;
      int j = ((ni & 1) << 1) + thi;
      int u0 = (tlow << 2) + ((ni >> 1) & 1) + ((ni >> 2) << 3);
      int a0 = (w16 + g) * 68 + u0 * 4 + j;
      int a1 = (w16 + g + 8) * 68 + u0 * 4 + j;
      sK[a0] = f2tf(p0);
      sK[a0 + 8] = f2tf(p1);   // u0+2 -> +8 words
      sK[a1] = f2tf(p2);
      sK[a1 + 8] = f2tf(p3);
    }
    rs0 += __shfl_xor_sync(0xffffffffu, rs0, 1);
    rs0 += __shfl_xor_sync(0xffffffffu, rs0, 2);
    rs1 += __shfl_xor_sync(0xffffffffu, rs1, 1);
    rs1 += __shfl_xor_sync(0xffffffffu, rs1, 2);
    l0 = l0 * al0 + rs0;
    l1 = l1 * al1 + rs1;
#pragma unroll
    for (int ni = 0; ni < 8; ++ni) {
      o[ni][0] *= al0;
      o[ni][1] *= al0;
      o[ni][2] *= al1;
      o[ni][3] *= al1;
    }
    __syncwarp();

    // ---- O += P V ----
#pragma unroll
    for (int kk2 = 0; kk2 < 4; ++kk2) {
      int u4 = (tg * 2 + (kk2 & 1) + ((kk2 >> 1) << 3)) * 4;
      uint4 q0v = *reinterpret_cast<const uint4*>(sK + (w16 + g) * 68 + u4);
      uint4 q1v = *reinterpret_cast<const uint4*>(sK + (w16 + g + 8) * 68 + u4);
      uint32_t pae[4] = {q0v.x, q1v.x, q0v.y, q1v.y};
      uint32_t pao[4] = {q0v.z, q1v.z, q0v.w, q1v.w};
#pragma unroll
      for (int ni = 0; ni < 8; ++ni) {
        uint4 vb = *reinterpret_cast<const uint4*>(
            sV + (ni * 8 + g) * 68 + u4);
        mma8(o[ni], pae, vb.x, vb.y);
        mma8(o[ni], pao, vb.z, vb.w);
      }
    }
  }

  const float inv0 = 1.f / l0;
  const float inv1 = 1.f / l1;
#pragma unroll
  for (int ni = 0; ni < 8; ++ni) {
    int col = colh + ni * 8 + 2 * tg;
    float2 v0 = make_float2(o[ni][0] * inv0, o[ni][1] * inv0);
    float2 v1 = make_float2(o[ni][2] * inv1, o[ni][3] * inv1);
    *reinterpret_cast<float2*>(Og + (qrow0 + w16 + g) * kD + col) = v0;
    *reinterpret_cast<float2*>(Og + (qrow0 + w16 + g + 8) * kD + col) = v1;
  }
}

// ---------------------------------------------------------------------------
extern "C" void kernel_launch(void* const* d_in, const int* in_sizes, int n_in,
                              void* d_out, int out_size) {
  const float* skel = (const float*)d_in[0];
  const float* sens = (const float*)d_in[1];
  const int* mask_skel = (const int*)d_in[2];
  const int* mask_sens = (const int*)d_in[3];
  const float* Wq_s2e = (const float*)d_in[4];
  const float* Wk_e = (const float*)d_in[5];
  const float* Wv_e = (const float*)d_in[6];
  const float* Wq_e2s = (const float*)d_in[7];
  const float* Wk_s = (const float*)d_in[8];
  const float* Wv_s = (const float*)d_in[9];
  const float* Wo_s = (const float*)d_in[10];
  const float* Wo_e = (const float*)d_in[11];

  float* out_e2s = (float*)d_out;                     // tuple element 0
  float* out_s2e = (float*)d_out + (size_t)kM * kD;   // tuple element 1

  float *Qp, *Kp, *Vp, *Op;
  cudaGetSymbolAddress((void**)&Qp, g_Q);
  cudaGetSymbolAddress((void**)&Kp, g_K);
  cudaGetSymbolAddress((void**)&Vp, g_V);
  cudaGetSymbolAddress((void**)&Op, g_O);

  dim3 ggrid(kM / 128, kD / 128);  // 64 x 4
  dim3 agrid(kT / 64, kH, kB);     // 32 x 8 x 4

  // ---- s2e: skel queries attend over sensor K/V ----
  gemm_nt_tf32<<<ggrid, 256>>>(skel, Wq_s2e, Qp);
  gemm_nt_tf32<<<ggrid, 256>>>(sens, Wk_e, Kp);
  gemm_nt_tf32<<<ggrid, 256>>>(sens, Wv_e, Vp);
  attn_tf32<<<agrid, 128>>>(Qp, Kp, Vp, mask_sens, Op);
  gemm_nt_tf32<<<ggrid, 256>>>(Op, Wo_e, out_s2e);

  // ---- e2s: sensor queries attend over skeleton K/V ----
  gemm_nt_tf32<<<ggrid, 256>>>(sens, Wq_e2s, Qp);
  gemm_nt_tf32<<<ggrid, 256>>>(skel, Wk_s, Kp);
  gemm_nt_tf32<<<ggrid, 256>>>(skel, Wv_s, Vp);
  attn_tf32<<<agrid, 128>>>(Qp, Kp, Vp, mask_skel, Op);
  gemm_nt_tf32<<<ggrid, 256>>>(Op, Wo_s, out_e2s);
}

// round 3
// speedup vs baseline: 1.5544x; 1.5544x over previous
#include <cuda_runtime.h>
#include <cstdint>
#include <cstddef>

// ---------------------------------------------------------------------------
// Dual cross-attention (e2s, s2e), tf32 mma.sync.
// R3: 8-warp/128-query attention CTAs, double-buffered K/V, STS.128 staging,
// XOR-swizzled P buffer, one barrier per KV chunk. Fragment reads keep the
// R1 conflict-free LDS.32 patterns (bank = 4g+tg / 8tg+g / 8g+tg^swz).
// ---------------------------------------------------------------------------

constexpr int kB = 4;
constexpr int kT = 2048;
constexpr int kD = 512;
constexpr int kH = 8;
constexpr int kDK = 64;
constexpr int kM = kB * kT;  // 8192 rows
constexpr float kSmScale = 1.5f / 8.0f;  // SCALE / sqrt(DK)
constexpr float kLog2e = 1.4426950408889634f;

__device__ float g_Q[(size_t)kM * kD];
__device__ float g_K[(size_t)kM * kD];
__device__ float g_V[(size_t)kM * kD];
__device__ float g_O[(size_t)kM * kD];

__device__ __forceinline__ uint32_t f2tf(float f) {
  uint32_t u;
  asm("cvt.rna.tf32.f32 %0, %1;" : "=r"(u) : "f"(f));
  return u;
}

__device__ __forceinline__ void st64(uint32_t* p, uint32_t a, uint32_t b) {
  *reinterpret_cast<uint2*>(p) = make_uint2(a, b);
}

__device__ __forceinline__ void st128(uint32_t* p, float4 v) {
  uint4 t = make_uint4(f2tf(v.x), f2tf(v.y), f2tf(v.z), f2tf(v.w));
  *reinterpret_cast<uint4*>(p) = t;
}

// D += A(16x8, row) * B(8x8, col), tf32 in, fp32 accum.
__device__ __forceinline__ void mma8(float* d, const uint32_t* a, uint32_t b0,
                                     uint32_t b1) {
  asm volatile(
      "mma.sync.aligned.m16n8k8.row.col.f32.tf32.tf32.f32 "
      "{%0,%1,%2,%3}, {%4,%5,%6,%7}, {%8,%9}, {%0,%1,%2,%3};\n"
      : "+f"(d[0]), "+f"(d[1]), "+f"(d[2]), "+f"(d[3])
      : "r"(a[0]), "r"(a[1]), "r"(a[2]), "r"(a[3]), "r"(b0), "r"(b1));
}

// ---------------------------------------------------------------------------
// C[8192,512] = A[8192,512] @ W[512,512]^T. CTA 128x128, k-tile 32,
// 8 warps = 4(M) x 2(N). Double-buffered smem, STS.128 staging, 1 bar/ktile.
// Dynamic smem words: A0[128*36] A1[128*36] B0[128*36] B1[128*36] = 18432 w.
// ---------------------------------------------------------------------------
__global__ void __launch_bounds__(256, 2)
    gemm_nt_tf32(const float* __restrict__ A, const float* __restrict__ W,
                 float* __restrict__ C) {
  extern __shared__ uint32_t gsm[];

  const int tid = threadIdx.x;
  const int lane = tid & 31;
  const int wid = tid >> 5;
  const int wm = wid & 3;
  const int wn = wid >> 2;
  const int g = lane >> 2;
  const int tg = lane & 3;
  const int m0 = blockIdx.x * 128;
  const int n0 = blockIdx.y * 128;

  float acc[2][8][4];
#pragma unroll
  for (int mi = 0; mi < 2; ++mi)
#pragma unroll
    for (int ni = 0; ni < 8; ++ni)
#pragma unroll
      for (int c = 0; c < 4; ++c) acc[mi][ni][c] = 0.f;

  // stage k-tile kt into buffer buf
  auto stage = [&](int kt, int buf) {
    uint32_t* sA = gsm + buf * 4608;
    uint32_t* sB = gsm + 9216 + buf * 4608;
#pragma unroll
    for (int it = 0; it < 4; ++it) {
      int task = it * 256 + tid;  // 1024 tasks: row(7b) x quad(3b)
      int row = task >> 3;
      int q = task & 7;
      float4 va = *reinterpret_cast<const float4*>(
          A + (size_t)(m0 + row) * kD + kt * 32 + q * 4);
      st128(sA + row * 36 + q * 4, va);
      float4 vb = *reinterpret_cast<const float4*>(
          W + (size_t)(n0 + row) * kD + kt * 32 + q * 4);
      st128(sB + row * 36 + q * 4, vb);
    }
  };

  stage(0, 0);
  __syncthreads();

  for (int kt = 0; kt < 16; ++kt) {
    const int p = kt & 1;
    const uint32_t* sA = gsm + p * 4608;
    const uint32_t* sB = gsm + 9216 + p * 4608;
#pragma unroll
    for (int kk = 0; kk < 4; ++kk) {
      uint32_t a[2][4];
#pragma unroll
      for (int mi = 0; mi < 2; ++mi) {
        int rb = wm * 32 + mi * 16;
        a[mi][0] = sA[(rb + g) * 36 + kk * 8 + tg];
        a[mi][1] = sA[(rb + g + 8) * 36 + kk * 8 + tg];
        a[mi][2] = sA[(rb + g) * 36 + kk * 8 + tg + 4];
        a[mi][3] = sA[(rb + g + 8) * 36 + kk * 8 + tg + 4];
      }
#pragma unroll
      for (int ni = 0; ni < 8; ++ni) {
        int rb = wn * 64 + ni * 8 + g;
        uint32_t b0 = sB[rb * 36 + kk * 8 + tg];
        uint32_t b1 = sB[rb * 36 + kk * 8 + tg + 4];
        mma8(acc[0][ni], a[0], b0, b1);
        mma8(acc[1][ni], a[1], b0, b1);
      }
    }
    if (kt < 15) stage(kt + 1, 1 - p);
    __syncthreads();
  }

#pragma unroll
  for (int mi = 0; mi < 2; ++mi) {
    int row = m0 + wm * 32 + mi * 16 + g;
#pragma unroll
    for (int ni = 0; ni < 8; ++ni) {
      int col = n0 + wn * 64 + ni * 8 + 2 * tg;
      float2 v0 = make_float2(acc[mi][ni][0], acc[mi][ni][1]);
      float2 v1 = make_float2(acc[mi][ni][2], acc[mi][ni][3]);
      *reinterpret_cast<float2*>(C + (size_t)row * kD + col) = v0;
      *reinterpret_cast<float2*>(C + (size_t)(row + 8) * kD + col) = v1;
    }
  }
}

// ---------------------------------------------------------------------------
// Flash attention: CTA = (128-query tile, head, batch), 8 warps x 16 rows.
// Dynamic smem (words):
//   sK[2][64*68]  @ 0      (K chunk, tf32)
//   sV[2][64*72]  @ 8704   (V chunk, tf32)
//   sP[128*72]    @ 17920  (Q staging, then P tiles; XOR-4 column swizzle)
//   bias[2][64]   @ 27136  (float)
// Total 27264 words = 109056 B.
// ---------------------------------------------------------------------------
constexpr int kSKOff = 0;
constexpr int kSVOff = 8704;
constexpr int kSPOff = 17920;
constexpr int kBiasOff = 27136;
constexpr int kAttnSmem = 27264 * 4;

__global__ void __launch_bounds__(256, 2)
    attn_tf32(const float* __restrict__ Qg, const float* __restrict__ Kg,
              const float* __restrict__ Vg, const int* __restrict__ mask,
              float* __restrict__ Og) {
  extern __shared__ uint32_t asm_[];
  uint32_t* sP = asm_ + kSPOff;
  float* sBias = reinterpret_cast<float*>(asm_ + kBiasOff);

  const int tid = threadIdx.x;
  const int lane = tid & 31;
  const int w = tid >> 5;
  const int g = lane >> 2;
  const int tg = lane & 3;
  const int bb = blockIdx.z;
  const int h = blockIdx.y;
  const int q0 = blockIdx.x * 128;
  const int colh = h * kDK;
  const size_t qrow0 = (size_t)bb * kT + q0;
  const size_t kvrow0 = (size_t)bb * kT;
  const int w16 = w * 16;
  const int swz = (g >> 2) << 2;  // 0 for g<4, 4 for g>=4

  // stage K/V chunk j (64 keys) + bias into buffer buf
  auto stage = [&](int j, int buf) {
    uint32_t* sk = asm_ + kSKOff + buf * 4352;
    uint32_t* sv = asm_ + kSVOff + buf * 4608;
#pragma unroll
    for (int it = 0; it < 4; ++it) {
      int task = it * 256 + tid;  // 1024: row(6b) x quad(4b)
      int row = task >> 4;
      int q = task & 15;
      float4 vk = *reinterpret_cast<const float4*>(
          Kg + (kvrow0 + j * 64 + row) * kD + colh + q * 4);
      st128(sk + row * 68 + q * 4, vk);
      float4 vv = *reinterpret_cast<const float4*>(
          Vg + (kvrow0 + j * 64 + row) * kD + colh + q * 4);
      st128(sv + row * 72 + q * 4, vv);
    }
    if (tid < 64)
      sBias[buf * 64 + tid] =
          mask[kvrow0 + j * 64 + tid] ? 0.f : -1.4426950e30f;
  };

  // ---- stage Q (128x64) into sP, stage chunk 0, then lift Q fragments ----
#pragma unroll
  for (int it = 0; it < 8; ++it) {
    int task = it * 256 + tid;  // 2048: row(7b) x quad(4b)
    int row = task >> 4;
    int q = task & 15;
    float4 v = *reinterpret_cast<const float4*>(
        Qg + (qrow0 + row) * kD + colh + q * 4);
    st128(sP + row * 72 + q * 4, v);
  }
  stage(0, 0);
  __syncthreads();

  uint32_t aq[8][4];
#pragma unroll
  for (int kk = 0; kk < 8; ++kk) {
    aq[kk][0] = sP[(w16 + g) * 72 + kk * 8 + tg];
    aq[kk][1] = sP[(w16 + g + 8) * 72 + kk * 8 + tg];
    aq[kk][2] = sP[(w16 + g) * 72 + kk * 8 + tg + 4];
    aq[kk][3] = sP[(w16 + g + 8) * 72 + kk * 8 + tg + 4];
  }

  float o[8][4];
#pragma unroll
  for (int ni = 0; ni < 8; ++ni)
#pragma unroll
    for (int c = 0; c < 4; ++c) o[ni][c] = 0.f;
  float mrow0 = -INFINITY, mrow1 = -INFINITY;
  float l0 = 0.f, l1 = 0.f;
  const float sc = kSmScale * kLog2e;

  for (int j = 0; j < kT / 64; ++j) {
    const int p = j & 1;
    const uint32_t* sk = asm_ + kSKOff + p * 4352;
    const uint32_t* sv = asm_ + kSVOff + p * 4608;
    const float* bias = sBias + p * 64;

    // ---- S = Q K^T (16 rows x 64 keys per warp) ----
    float s[8][4];
#pragma unroll
    for (int ni = 0; ni < 8; ++ni)
#pragma unroll
      for (int c = 0; c < 4; ++c) s[ni][c] = 0.f;
#pragma unroll
    for (int kk = 0; kk < 8; ++kk)
#pragma unroll
      for (int ni = 0; ni < 8; ++ni) {
        uint32_t b0 = sk[(ni * 8 + g) * 68 + kk * 8 + tg];
        uint32_t b1 = sk[(ni * 8 + g) * 68 + kk * 8 + tg + 4];
        mma8(s[ni], aq[kk], b0, b1);
      }

    // ---- scale + mask bias, row max ----
    float mx0 = -INFINITY, mx1 = -INFINITY;
#pragma unroll
    for (int ni = 0; ni < 8; ++ni) {
      float bb0 = bias[ni * 8 + 2 * tg];
      float bb1 = bias[ni * 8 + 2 * tg + 1];
      s[ni][0] = s[ni][0] * sc + bb0;
      s[ni][1] = s[ni][1] * sc + bb1;
      s[ni][2] = s[ni][2] * sc + bb0;
      s[ni][3] = s[ni][3] * sc + bb1;
      mx0 = fmaxf(mx0, fmaxf(s[ni][0], s[ni][1]));
      mx1 = fmaxf(mx1, fmaxf(s[ni][2], s[ni][3]));
    }
    mx0 = fmaxf(mx0, __shfl_xor_sync(0xffffffffu, mx0, 1));
    mx0 = fmaxf(mx0, __shfl_xor_sync(0xffffffffu, mx0, 2));
    mx1 = fmaxf(mx1, __shfl_xor_sync(0xffffffffu, mx1, 1));
    mx1 = fmaxf(mx1, __shfl_xor_sync(0xffffffffu, mx1, 2));
    float mn0 = fmaxf(mrow0, mx0);
    float mn1 = fmaxf(mrow1, mx1);
    float al0 = exp2f(mrow0 - mn0);
    float al1 = exp2f(mrow1 - mn1);
    mrow0 = mn0;
    mrow1 = mn1;

    // ---- exp2, write P into sP (warp-private rows, XOR-4 swizzle) ----
    __syncwarp();
    float rs0 = 0.f, rs1 = 0.f;
#pragma unroll
    for (int ni = 0; ni < 8; ++ni) {
      float p0 = exp2f(s[ni][0] - mn0);
      float p1 = exp2f(s[ni][1] - mn0);
      float p2 = exp2f(s[ni][2] - mn1);
      float p3 = exp2f(s[ni][3] - mn1);
      rs0 += p0 + p1;
      rs1 += p2 + p3;
      int c0 = (ni * 8) + ((2 * tg) ^ swz);
      st64(sP + (w16 + g) * 72 + c0, f2tf(p0), f2tf(p1));
      st64(sP + (w16 + g + 8) * 72 + c0, f2tf(p2), f2tf(p3));
    }
    rs0 += __shfl_xor_sync(0xffffffffu, rs0, 1);
    rs0 += __shfl_xor_sync(0xffffffffu, rs0, 2);
    rs1 += __shfl_xor_sync(0xffffffffu, rs1, 1);
    rs1 += __shfl_xor_sync(0xffffffffu, rs1, 2);
    l0 = l0 * al0 + rs0;
    l1 = l1 * al1 + rs1;
#pragma unroll
    for (int ni = 0; ni < 8; ++ni) {
      o[ni][0] *= al0;
      o[ni][1] *= al0;
      o[ni][2] *= al1;
      o[ni][3] *= al1;
    }
    __syncwarp();

    // ---- O += P V ----
#pragma unroll
    for (int kk = 0; kk < 8; ++kk) {
      int cc = kk * 8 + (tg ^ swz);   // holds original col kk*8+tg
      int cc4 = cc ^ 4;               // holds original col kk*8+tg+4
      uint32_t pa[4];
      pa[0] = sP[(w16 + g) * 72 + cc];
      pa[1] = sP[(w16 + g + 8) * 72 + cc];
      pa[2] = sP[(w16 + g) * 72 + cc4];
      pa[3] = sP[(w16 + g + 8) * 72 + cc4];
#pragma unroll
      for (int ni = 0; ni < 8; ++ni) {
        uint32_t b0 = sv[(kk * 8 + tg) * 72 + ni * 8 + g];
        uint32_t b1 = sv[(kk * 8 + tg + 4) * 72 + ni * 8 + g];
        mma8(o[ni], pa, b0, b1);
      }
    }

    // ---- prefetch next chunk into the other buffer, single barrier ----
    if (j + 1 < kT / 64) stage(j + 1, 1 - p);
    __syncthreads();
  }

  const float inv0 = 1.f / l0;
  const float inv1 = 1.f / l1;
#pragma unroll
  for (int ni = 0; ni < 8; ++ni) {
    int col = colh + ni * 8 + 2 * tg;
    float2 v0 = make_float2(o[ni][0] * inv0, o[ni][1] * inv0);
    float2 v1 = make_float2(o[ni][2] * inv1, o[ni][3] * inv1);
    *reinterpret_cast<float2*>(Og + (qrow0 + w16 + g) * kD + col) = v0;
    *reinterpret_cast<float2*>(Og + (qrow0 + w16 + g + 8) * kD + col) = v1;
  }
}

// ---------------------------------------------------------------------------
extern "C" void kernel_launch(void* const* d_in, const int* in_sizes, int n_in,
                              void* d_out, int out_size) {
  const float* skel = (const float*)d_in[0];
  const float* sens = (const float*)d_in[1];
  const int* mask_skel = (const int*)d_in[2];
  const int* mask_sens = (const int*)d_in[3];
  const float* Wq_s2e = (const float*)d_in[4];
  const float* Wk_e = (const float*)d_in[5];
  const float* Wv_e = (const float*)d_in[6];
  const float* Wq_e2s = (const float*)d_in[7];
  const float* Wk_s = (const float*)d_in[8];
  const float* Wv_s = (const float*)d_in[9];
  const float* Wo_s = (const float*)d_in[10];
  const float* Wo_e = (const float*)d_in[11];

  float* out_e2s = (float*)d_out;                     // tuple element 0
  float* out_s2e = (float*)d_out + (size_t)kM * kD;   // tuple element 1

  float *Qp, *Kp, *Vp, *Op;
  cudaGetSymbolAddress((void**)&Qp, g_Q);
  cudaGetSymbolAddress((void**)&Kp, g_K);
  cudaGetSymbolAddress((void**)&Vp, g_V);
  cudaGetSymbolAddress((void**)&Op, g_O);

  const int kGemmSmem = 18432 * 4;  // 73728 B
  static bool attr_done = false;
  if (!attr_done) {
    cudaFuncSetAttribute(gemm_nt_tf32,
                         cudaFuncAttributeMaxDynamicSharedMemorySize,
                         kGemmSmem);
    cudaFuncSetAttribute(attn_tf32,
                         cudaFuncAttributeMaxDynamicSharedMemorySize,
                         kAttnSmem);
    attr_done = true;
  }

  dim3 ggrid(kM / 128, kD / 128);  // 64 x 4
  dim3 agrid(kT / 128, kH, kB);    // 16 x 8 x 4

  // ---- s2e: skel queries attend over sensor K/V ----
  gemm_nt_tf32<<<ggrid, 256, kGemmSmem>>>(skel, Wq_s2e, Qp);
  gemm_nt_tf32<<<ggrid, 256, kGemmSmem>>>(sens, Wk_e, Kp);
  gemm_nt_tf32<<<ggrid, 256, kGemmSmem>>>(sens, Wv_e, Vp);
  attn_tf32<<<agrid, 256, kAttnSmem>>>(Qp, Kp, Vp, mask_sens, Op);
  gemm_nt_tf32<<<ggrid, 256, kGemmSmem>>>(Op, Wo_e, out_s2e);

  // ---- e2s: sensor queries attend over skeleton K/V ----
  gemm_nt_tf32<<<ggrid, 256, kGemmSmem>>>(sens, Wq_e2s, Qp);
  gemm_nt_tf32<<<ggrid, 256, kGemmSmem>>>(skel, Wk_s, Kp);
  gemm_nt_tf32<<<ggrid, 256, kGemmSmem>>>(skel, Wv_s, Vp);
  attn_tf32<<<agrid, 256, kAttnSmem>>>(Qp, Kp, Vp, mask_skel, Op);
  gemm_nt_tf32<<<ggrid, 256, kGemmSmem>>>(Op, Wo_s, out_e2s);
}

// round 5
// speedup vs baseline: 1.7208x; 1.1071x over previous
#include <cuda_runtime.h>
#include <cstdint>
#include <cstddef>

// ---------------------------------------------------------------------------
// Dual cross-attention (e2s, s2e), tf32 mma.sync (tcgen05 unavailable: harness
// PTX targets compute_103 without the 'a' feature set).
// R5: R1 GEMM (+tf32-rounding epilogue for Q/K/V) + R3 attention with
// cp.async staging of pre-rounded operands (no cvt in attention, copies
// overlap softmax/PV). Numerically bit-identical to R1/R3 (rel_err 8.1e-4).
// ---------------------------------------------------------------------------

constexpr int kB = 4;
constexpr int kT = 2048;
constexpr int kD = 512;
constexpr int kH = 8;
constexpr int kDK = 64;
constexpr int kM = kB * kT;  // 8192 rows
constexpr float kSmScale = 1.5f / 8.0f;  // SCALE / sqrt(DK)
constexpr float kLog2e = 1.4426950408889634f;

__device__ float g_Q[(size_t)kM * kD];
__device__ float g_K[(size_t)kM * kD];
__device__ float g_V[(size_t)kM * kD];
__device__ float g_O[(size_t)kM * kD];

__device__ __forceinline__ uint32_t f2tf(float f) {
  uint32_t u;
  asm("cvt.rna.tf32.f32 %0, %1;" : "=r"(u) : "f"(f));
  return u;
}

__device__ __forceinline__ uint32_t smem_u32(const void* p) {
  uint32_t a;
  asm("{ .reg .u64 t; cvta.to.shared.u64 t, %1; cvt.u32.u64 %0, t; }"
      : "=r"(a) : "l"(p));
  return a;
}

__device__ __forceinline__ void cpa16(uint32_t dst, const void* src) {
  asm volatile("cp.async.cg.shared.global [%0], [%1], 16;"
               :: "r"(dst), "l"(src));
}
#define CP_COMMIT() asm volatile("cp.async.commit_group;" ::: "memory")
#define CP_WAIT0() asm volatile("cp.async.wait_group 0;" ::: "memory")

__device__ __forceinline__ void st64(uint32_t* p, uint32_t a, uint32_t b) {
  *reinterpret_cast<uint2*>(p) = make_uint2(a, b);
}

// D += A(16x8, row) * B(8x8, col), tf32 in, fp32 accum.
__device__ __forceinline__ void mma8(float* d, const uint32_t* a, uint32_t b0,
                                     uint32_t b1) {
  asm volatile(
      "mma.sync.aligned.m16n8k8.row.col.f32.tf32.tf32.f32 "
      "{%0,%1,%2,%3}, {%4,%5,%6,%7}, {%8,%9}, {%0,%1,%2,%3};\n"
      : "+f"(d[0]), "+f"(d[1]), "+f"(d[2]), "+f"(d[3])
      : "r"(a[0]), "r"(a[1]), "r"(a[2]), "r"(a[3]), "r"(b0), "r"(b1));
}

// ---------------------------------------------------------------------------
// C[8192,512] = A[8192,512] @ W[512,512]^T   (R1 GEMM, proven).
// If round_out != 0, C is stored tf32-rounded (bit patterns valid fp32) so
// downstream attention staging can copy without converting.
// ---------------------------------------------------------------------------
__global__ void __launch_bounds__(256, 2)
    gemm_nt_tf32(const float* __restrict__ A, const float* __restrict__ W,
                 float* __restrict__ C, int round_out) {
  __shared__ uint32_t sA[128][36];
  __shared__ uint32_t sB[128][36];

  const int tid = threadIdx.x;
  const int lane = tid & 31;
  const int wid = tid >> 5;
  const int wm = wid & 3;
  const int wn = wid >> 2;
  const int g = lane >> 2;
  const int tg = lane & 3;
  const int m0 = blockIdx.x * 128;
  const int n0 = blockIdx.y * 128;

  float acc[2][8][4];
#pragma unroll
  for (int mi = 0; mi < 2; ++mi)
#pragma unroll
    for (int ni = 0; ni < 8; ++ni)
#pragma unroll
      for (int c = 0; c < 4; ++c) acc[mi][ni][c] = 0.f;

  const int lrow = tid >> 3;
  const int lcol = (tid & 7) * 4;

  for (int k0 = 0; k0 < kD; k0 += 32) {
    __syncthreads();
#pragma unroll
    for (int r = 0; r < 4; ++r) {
      int row = lrow + r * 32;
      float4 va = *reinterpret_cast<const float4*>(
          A + (size_t)(m0 + row) * kD + k0 + lcol);
      sA[row][lcol + 0] = f2tf(va.x);
      sA[row][lcol + 1] = f2tf(va.y);
      sA[row][lcol + 2] = f2tf(va.z);
      sA[row][lcol + 3] = f2tf(va.w);
      float4 vb = *reinterpret_cast<const float4*>(
          W + (size_t)(n0 + row) * kD + k0 + lcol);
      sB[row][lcol + 0] = f2tf(vb.x);
      sB[row][lcol + 1] = f2tf(vb.y);
      sB[row][lcol + 2] = f2tf(vb.z);
      sB[row][lcol + 3] = f2tf(vb.w);
    }
    __syncthreads();
#pragma unroll
    for (int kk = 0; kk < 4; ++kk) {
      uint32_t a[2][4];
#pragma unroll
      for (int mi = 0; mi < 2; ++mi) {
        int rb = wm * 32 + mi * 16;
        a[mi][0] = sA[rb + g][kk * 8 + tg];
        a[mi][1] = sA[rb + g + 8][kk * 8 + tg];
        a[mi][2] = sA[rb + g][kk * 8 + tg + 4];
        a[mi][3] = sA[rb + g + 8][kk * 8 + tg + 4];
      }
      uint32_t bf[8][2];
#pragma unroll
      for (int ni = 0; ni < 8; ++ni) {
        int rb = wn * 64 + ni * 8 + g;
        bf[ni][0] = sB[rb][kk * 8 + tg];
        bf[ni][1] = sB[rb][kk * 8 + tg + 4];
      }
#pragma unroll
      for (int mi = 0; mi < 2; ++mi)
#pragma unroll
        for (int ni = 0; ni < 8; ++ni)
          mma8(acc[mi][ni], a[mi], bf[ni][0], bf[ni][1]);
    }
  }

#pragma unroll
  for (int mi = 0; mi < 2; ++mi) {
    int row = m0 + wm * 32 + mi * 16 + g;
#pragma unroll
    for (int ni = 0; ni < 8; ++ni) {
      int col = n0 + wn * 64 + ni * 8 + 2 * tg;
      float2 v0, v1;
      if (round_out) {
        v0 = make_float2(__uint_as_float(f2tf(acc[mi][ni][0])),
                         __uint_as_float(f2tf(acc[mi][ni][1])));
        v1 = make_float2(__uint_as_float(f2tf(acc[mi][ni][2])),
                         __uint_as_float(f2tf(acc[mi][ni][3])));
      } else {
        v0 = make_float2(acc[mi][ni][0], acc[mi][ni][1]);
        v1 = make_float2(acc[mi][ni][2], acc[mi][ni][3]);
      }
      *reinterpret_cast<float2*>(C + (size_t)row * kD + col) = v0;
      *reinterpret_cast<float2*>(C + (size_t)(row + 8) * kD + col) = v1;
    }
  }
}

// ---------------------------------------------------------------------------
// Flash attention: CTA = (128-query tile, head, batch), 8 warps x 16 rows.
// Inputs already tf32-rounded -> staging is raw cp.async copies overlapped
// with softmax + PV of the current chunk.
// Dynamic smem (words):
//   sK[2][64*68] @ 0, sV[2][64*72] @ 8704, sP[128*72] @ 17920 (Q stage + P),
//   bias[2][64] @ 27136.  Total 27264 words = 109056 B.
// ---------------------------------------------------------------------------
constexpr int kSKOff = 0;
constexpr int kSVOff = 8704;
constexpr int kSPOff = 17920;
constexpr int kBiasOff = 27136;
constexpr int kAttnSmem = 27264 * 4;

__global__ void __launch_bounds__(256, 2)
    attn_tf32(const float* __restrict__ Qg, const float* __restrict__ Kg,
              const float* __restrict__ Vg, const int* __restrict__ mask,
              float* __restrict__ Og) {
  extern __shared__ uint32_t asm_[];
  uint32_t* sP = asm_ + kSPOff;
  float* sBias = reinterpret_cast<float*>(asm_ + kBiasOff);

  const int tid = threadIdx.x;
  const int lane = tid & 31;
  const int w = tid >> 5;
  const int g = lane >> 2;
  const int tg = lane & 3;
  const int bb = blockIdx.z;
  const int h = blockIdx.y;
  const int q0 = blockIdx.x * 128;
  const int colh = h * kDK;
  const size_t qrow0 = (size_t)bb * kT + q0;
  const size_t kvrow0 = (size_t)bb * kT;
  const int w16 = w * 16;
  const int swz = (g >> 2) << 2;  // 0 for g<4, 4 for g>=4

  const uint32_t smem_base = smem_u32(asm_);
  const uint32_t skb = smem_base + kSKOff * 4;
  const uint32_t svb = smem_base + kSVOff * 4;
  const uint32_t spb = smem_base + kSPOff * 4;

  // row/quad decomposition for staging tasks
  const int srow = tid >> 4;      // 0..15
  const int sq4 = (tid & 15) * 4; // quad word offset 0..60

  // stage K/V chunk j (64 keys) into buffer buf via cp.async (raw copies)
  auto stage_async = [&](int j, int buf) {
    uint32_t skd = skb + (buf * 4352 + srow * 68 + sq4) * 4;
    uint32_t svd = svb + (buf * 4608 + srow * 72 + sq4) * 4;
    const float* ks = Kg + (kvrow0 + j * 64 + srow) * kD + colh + sq4;
    const float* vs = Vg + (kvrow0 + j * 64 + srow) * kD + colh + sq4;
#pragma unroll
    for (int r = 0; r < 4; ++r) {  // rows srow, srow+16, +32, +48
      cpa16(skd, ks);
      cpa16(svd, vs);
      skd += 16 * 68 * 4;
      svd += 16 * 72 * 4;
      ks += 16 * kD;
      vs += 16 * kD;
    }
    if (tid < 64)
      sBias[buf * 64 + tid] =
          mask[kvrow0 + j * 64 + tid] ? 0.f : -1.4426950e30f;
    CP_COMMIT();
  };

  // ---- stage Q (128x64) into sP + chunk 0 via cp.async ----
  {
    uint32_t spd = spb + (srow * 72 + sq4) * 4;
    const float* qs = Qg + (qrow0 + srow) * kD + colh + sq4;
#pragma unroll
    for (int r = 0; r < 8; ++r) {
      cpa16(spd, qs);
      spd += 16 * 72 * 4;
      qs += 16 * kD;
    }
    CP_COMMIT();
  }
  stage_async(0, 0);
  CP_WAIT0();
  __syncthreads();

  // ---- lift Q register fragments (warp-private rows of sP) ----
  uint32_t aq[8][4];
#pragma unroll
  for (int kk = 0; kk < 8; ++kk) {
    aq[kk][0] = sP[(w16 + g) * 72 + kk * 8 + tg];
    aq[kk][1] = sP[(w16 + g + 8) * 72 + kk * 8 + tg];
    aq[kk][2] = sP[(w16 + g) * 72 + kk * 8 + tg + 4];
    aq[kk][3] = sP[(w16 + g + 8) * 72 + kk * 8 + tg + 4];
  }

  float o[8][4];
#pragma unroll
  for (int ni = 0; ni < 8; ++ni)
#pragma unroll
    for (int c = 0; c < 4; ++c) o[ni][c] = 0.f;
  float mrow0 = -INFINITY, mrow1 = -INFINITY;
  float l0 = 0.f, l1 = 0.f;
  const float sc = kSmScale * kLog2e;

  for (int j = 0; j < kT / 64; ++j) {
    const int p = j & 1;
    const uint32_t* sk = asm_ + kSKOff + p * 4352;
    const uint32_t* sv = asm_ + kSVOff + p * 4608;
    const float* bias = sBias + p * 64;

    // ---- S = Q K^T (16 rows x 64 keys per warp) ----
    float s[8][4];
#pragma unroll
    for (int ni = 0; ni < 8; ++ni)
#pragma unroll
      for (int c = 0; c < 4; ++c) s[ni][c] = 0.f;
#pragma unroll
    for (int kk = 0; kk < 8; ++kk)
#pragma unroll
      for (int ni = 0; ni < 8; ++ni) {
        uint32_t b0 = sk[(ni * 8 + g) * 68 + kk * 8 + tg];
        uint32_t b1 = sk[(ni * 8 + g) * 68 + kk * 8 + tg + 4];
        mma8(s[ni], aq[kk], b0, b1);
      }

    // ---- kick off next chunk's staging; overlaps softmax + PV ----
    if (j + 1 < kT / 64) stage_async(j + 1, 1 - p);

    // ---- scale + mask bias, row max ----
    float mx0 = -INFINITY, mx1 = -INFINITY;
#pragma unroll
    for (int ni = 0; ni < 8; ++ni) {
      float bb0 = bias[ni * 8 + 2 * tg];
      float bb1 = bias[ni * 8 + 2 * tg + 1];
      s[ni][0] = s[ni][0] * sc + bb0;
      s[ni][1] = s[ni][1] * sc + bb1;
      s[ni][2] = s[ni][2] * sc + bb0;
      s[ni][3] = s[ni][3] * sc + bb1;
      mx0 = fmaxf(mx0, fmaxf(s[ni][0], s[ni][1]));
      mx1 = fmaxf(mx1, fmaxf(s[ni][2], s[ni][3]));
    }
    mx0 = fmaxf(mx0, __shfl_xor_sync(0xffffffffu, mx0, 1));
    mx0 = fmaxf(mx0, __shfl_xor_sync(0xffffffffu, mx0, 2));
    mx1 = fmaxf(mx1, __shfl_xor_sync(0xffffffffu, mx1, 1));
    mx1 = fmaxf(mx1, __shfl_xor_sync(0xffffffffu, mx1, 2));
    float mn0 = fmaxf(mrow0, mx0);
    float mn1 = fmaxf(mrow1, mx1);
    float al0 = exp2f(mrow0 - mn0);
    float al1 = exp2f(mrow1 - mn1);
    mrow0 = mn0;
    mrow1 = mn1;

    // ---- exp2, write P into sP (warp-private rows, XOR-4 swizzle) ----
    __syncwarp();
    float rs0 = 0.f, rs1 = 0.f;
#pragma unroll
    for (int ni = 0; ni < 8; ++ni) {
      float p0 = exp2f(s[ni][0] - mn0);
      float p1 = exp2f(s[ni][1] - mn0);
      float p2 = exp2f(s[ni][2] - mn1);
      float p3 = exp2f(s[ni][3] - mn1);
      rs0 += p0 + p1;
      rs1 += p2 + p3;
      int c0 = (ni * 8) + ((2 * tg) ^ swz);
      st64(sP + (w16 + g) * 72 + c0, f2tf(p0), f2tf(p1));
      st64(sP + (w16 + g + 8) * 72 + c0, f2tf(p2), f2tf(p3));
    }
    rs0 += __shfl_xor_sync(0xffffffffu, rs0, 1);
    rs0 += __shfl_xor_sync(0xffffffffu, rs0, 2);
    rs1 += __shfl_xor_sync(0xffffffffu, rs1, 1);
    rs1 += __shfl_xor_sync(0xffffffffu, rs1, 2);
    l0 = l0 * al0 + rs0;
    l1 = l1 * al1 + rs1;
#pragma unroll
    for (int ni = 0; ni < 8; ++ni) {
      o[ni][0] *= al0;
      o[ni][1] *= al0;
      o[ni][2] *= al1;
      o[ni][3] *= al1;
    }
    __syncwarp();

    // ---- O += P V ----
#pragma unroll
    for (int kk = 0; kk < 8; ++kk) {
      int cc = kk * 8 + (tg ^ swz);   // holds original col kk*8+tg
      int cc4 = cc ^ 4;               // holds original col kk*8+tg+4
      uint32_t pa[4];
      pa[0] = sP[(w16 + g) * 72 + cc];
      pa[1] = sP[(w16 + g + 8) * 72 + cc];
      pa[2] = sP[(w16 + g) * 72 + cc4];
      pa[3] = sP[(w16 + g + 8) * 72 + cc4];
#pragma unroll
      for (int ni = 0; ni < 8; ++ni) {
        uint32_t b0 = sv[(kk * 8 + tg) * 72 + ni * 8 + g];
        uint32_t b1 = sv[(kk * 8 + tg + 4) * 72 + ni * 8 + g];
        mma8(o[ni], pa, b0, b1);
      }
    }

    // ---- next chunk's cp.async copies done + visible ----
    CP_WAIT0();
    __syncthreads();
  }

  const float inv0 = 1.f / l0;
  const float inv1 = 1.f / l1;
#pragma unroll
  for (int ni = 0; ni < 8; ++ni) {
    int col = colh + ni * 8 + 2 * tg;
    float2 v0 = make_float2(o[ni][0] * inv0, o[ni][1] * inv0);
    float2 v1 = make_float2(o[ni][2] * inv1, o[ni][3] * inv1);
    *reinterpret_cast<float2*>(Og + (qrow0 + w16 + g) * kD + col) = v0;
    *reinterpret_cast<float2*>(Og + (qrow0 + w16 + g + 8) * kD + col) = v1;
  }
}

// ---------------------------------------------------------------------------
extern "C" void kernel_launch(void* const* d_in, const int* in_sizes, int n_in,
                              void* d_out, int out_size) {
  const float* skel = (const float*)d_in[0];
  const float* sens = (const float*)d_in[1];
  const int* mask_skel = (const int*)d_in[2];
  const int* mask_sens = (const int*)d_in[3];
  const float* Wq_s2e = (const float*)d_in[4];
  const float* Wk_e = (const float*)d_in[5];
  const float* Wv_e = (const float*)d_in[6];
  const float* Wq_e2s = (const float*)d_in[7];
  const float* Wk_s = (const float*)d_in[8];
  const float* Wv_s = (const float*)d_in[9];
  const float* Wo_s = (const float*)d_in[10];
  const float* Wo_e = (const float*)d_in[11];

  float* out_e2s = (float*)d_out;                     // tuple element 0
  float* out_s2e = (float*)d_out + (size_t)kM * kD;   // tuple element 1

  float *Qp, *Kp, *Vp, *Op;
  cudaGetSymbolAddress((void**)&Qp, g_Q);
  cudaGetSymbolAddress((void**)&Kp, g_K);
  cudaGetSymbolAddress((void**)&Vp, g_V);
  cudaGetSymbolAddress((void**)&Op, g_O);

  cudaFuncSetAttribute(attn_tf32, cudaFuncAttributeMaxDynamicSharedMemorySize,
                       kAttnSmem);

  dim3 ggrid(kM / 128, kD / 128);  // 64 x 4
  dim3 agrid(kT / 128, kH, kB);    // 16 x 8 x 4

  // ---- s2e: skel queries attend over sensor K/V ----
  gemm_nt_tf32<<<ggrid, 256>>>(skel, Wq_s2e, Qp, 1);
  gemm_nt_tf32<<<ggrid, 256>>>(sens, Wk_e, Kp, 1);
  gemm_nt_tf32<<<ggrid, 256>>>(sens, Wv_e, Vp, 1);
  attn_tf32<<<agrid, 256, kAttnSmem>>>(Qp, Kp, Vp, mask_sens, Op);
  gemm_nt_tf32<<<ggrid, 256>>>(Op, Wo_e, out_s2e, 0);

  // ---- e2s: sensor queries attend over skeleton K/V ----
  gemm_nt_tf32<<<ggrid, 256>>>(sens, Wq_e2s, Qp, 1);
  gemm_nt_tf32<<<ggrid, 256>>>(skel, Wk_s, Kp, 1);
  gemm_nt_tf32<<<ggrid, 256>>>(skel, Wv_s, Vp, 1);
  attn_tf32<<<agrid, 256, kAttnSmem>>>(Qp, Kp, Vp, mask_skel, Op);
  gemm_nt_tf32<<<ggrid, 256>>>(Op, Wo_s, out_e2s, 0);
}

// round 6
// speedup vs baseline: 3.0758x; 1.7874x over previous
#include <cuda_runtime.h>
#include <cuda_fp16.h>
#include <cstdint>
#include <cstddef>

// ---------------------------------------------------------------------------
// Dual cross-attention (e2s, s2e), fp16 mma.sync (m16n8k16, fp32 accum).
// fp16 mantissa == tf32 mantissa (10 bits) -> same rounding error as the
// proven tf32 version (8.1e-4), at 2x tensor throughput and half the SMEM
// bytes. P goes accumulator->A-fragment entirely in registers; V B-fragments
// via ldmatrix.trans; Q/K/V/O intermediates stored fp16 so all attention
// staging is raw cp.async.
// ---------------------------------------------------------------------------

constexpr int kB = 4;
constexpr int kT = 2048;
constexpr int kD = 512;
constexpr int kH = 8;
constexpr int kDK = 64;
constexpr int kM = kB * kT;  // 8192 rows
constexpr float kSmScale = 1.5f / 8.0f;  // SCALE / sqrt(DK)
constexpr float kLog2e = 1.4426950408889634f;

__device__ __half g_Q[(size_t)kM * kD];
__device__ __half g_K[(size_t)kM * kD];
__device__ __half g_V[(size_t)kM * kD];
__device__ __half g_O[(size_t)kM * kD];

__device__ __forceinline__ uint32_t f2h2(float lo, float hi) {
  uint32_t r;
  asm("cvt.rn.f16x2.f32 %0, %1, %2;" : "=r"(r) : "f"(hi), "f"(lo));
  return r;
}

__device__ __forceinline__ float ex2(float f) {
  float r;
  asm("ex2.approx.ftz.f32 %0, %1;" : "=f"(r) : "f"(f));
  return r;
}

__device__ __forceinline__ uint32_t smem_u32(const void* p) {
  uint32_t a;
  asm("{ .reg .u64 t; cvta.to.shared.u64 t, %1; cvt.u32.u64 %0, t; }"
      : "=r"(a) : "l"(p));
  return a;
}

__device__ __forceinline__ void cpa16(uint32_t dst, const void* src) {
  asm volatile("cp.async.cg.shared.global [%0], [%1], 16;"
               :: "r"(dst), "l"(src));
}
#define CP_COMMIT() asm volatile("cp.async.commit_group;" ::: "memory")
#define CP_WAIT0() asm volatile("cp.async.wait_group 0;" ::: "memory")

// D += A(16x16) * B(16x8), fp16 in, fp32 accum.
__device__ __forceinline__ void mma16(float* d, const uint32_t* a, uint32_t b0,
                                      uint32_t b1) {
  asm volatile(
      "mma.sync.aligned.m16n8k16.row.col.f32.f16.f16.f32 "
      "{%0,%1,%2,%3}, {%4,%5,%6,%7}, {%8,%9}, {%0,%1,%2,%3};\n"
      : "+f"(d[0]), "+f"(d[1]), "+f"(d[2]), "+f"(d[3])
      : "r"(a[0]), "r"(a[1]), "r"(a[2]), "r"(a[3]), "r"(b0), "r"(b1));
}

__device__ __forceinline__ void ldsm4t(uint32_t& r0, uint32_t& r1,
                                       uint32_t& r2, uint32_t& r3,
                                       uint32_t addr) {
  asm volatile(
      "ldmatrix.sync.aligned.m8n8.x4.trans.shared.b16 {%0,%1,%2,%3}, [%4];"
      : "=r"(r0), "=r"(r1), "=r"(r2), "=r"(r3) : "r"(addr));
}

// ---------------------------------------------------------------------------
// C[8192,512] = A[8192,512] @ W[512,512]^T, fp16 mma. CTA 128x128, k-tile 64,
// 8 warps = 4(M) x 2(N). SMEM rows: 32 half2-words + 4 pad (stride 36).
// A_HALF: A is fp16 (raw cp.async staging). OUT_HALF: C stored fp16.
// ---------------------------------------------------------------------------
template <bool A_HALF, bool OUT_HALF>
__global__ void __launch_bounds__(256, 2)
    gemm_f16(const void* __restrict__ Ap, const float* __restrict__ W,
             void* __restrict__ Cp) {
  __shared__ uint32_t sA[128 * 36];
  __shared__ uint32_t sB[128 * 36];

  const float* Af = (const float*)Ap;
  const __half* Ah = (const __half*)Ap;

  const int tid = threadIdx.x;
  const int lane = tid & 31;
  const int wid = tid >> 5;
  const int wm = wid & 3;
  const int wn = wid >> 2;
  const int g = lane >> 2;
  const int tg = lane & 3;
  const int m0 = blockIdx.x * 128;
  const int n0 = blockIdx.y * 128;

  float acc[2][8][4];
#pragma unroll
  for (int mi = 0; mi < 2; ++mi)
#pragma unroll
    for (int ni = 0; ni < 8; ++ni)
#pragma unroll
      for (int c = 0; c < 4; ++c) acc[mi][ni][c] = 0.f;

  const uint32_t sAb = smem_u32(sA);

  for (int kt = 0; kt < 8; ++kt) {
    __syncthreads();
    // ---- stage A k-tile (128 rows x 64 elems) ----
    if (A_HALF) {
#pragma unroll
      for (int it = 0; it < 4; ++it) {
        int task = it * 256 + tid;   // row(7b) x granule(3b)
        int row = task >> 3;
        int gr = task & 7;
        cpa16(sAb + (row * 36 + gr * 4) * 4,
              Ah + (size_t)(m0 + row) * kD + kt * 64 + gr * 8);
      }
      CP_COMMIT();
    } else {
#pragma unroll
      for (int it = 0; it < 4; ++it) {
        int task = it * 256 + tid;
        int row = task >> 3;
        int oc = task & 7;
        const float* pa = Af + (size_t)(m0 + row) * kD + kt * 64 + oc * 8;
        float4 v0 = *reinterpret_cast<const float4*>(pa);
        float4 v1 = *reinterpret_cast<const float4*>(pa + 4);
        *reinterpret_cast<uint4*>(sA + row * 36 + oc * 4) =
            make_uint4(f2h2(v0.x, v0.y), f2h2(v0.z, v0.w),
                       f2h2(v1.x, v1.y), f2h2(v1.z, v1.w));
      }
    }
    // ---- stage W k-tile (fp32 -> fp16) ----
#pragma unroll
    for (int it = 0; it < 4; ++it) {
      int task = it * 256 + tid;
      int row = task >> 3;
      int oc = task & 7;
      const float* pb = W + (size_t)(n0 + row) * kD + kt * 64 + oc * 8;
      float4 v0 = *reinterpret_cast<const float4*>(pb);
      float4 v1 = *reinterpret_cast<const float4*>(pb + 4);
      *reinterpret_cast<uint4*>(sB + row * 36 + oc * 4) =
          make_uint4(f2h2(v0.x, v0.y), f2h2(v0.z, v0.w),
                     f2h2(v1.x, v1.y), f2h2(v1.z, v1.w));
    }
    if (A_HALF) CP_WAIT0();
    __syncthreads();

    // ---- compute: 4 k-blocks of 16 ----
#pragma unroll
    for (int kk = 0; kk < 4; ++kk) {
      uint32_t a[2][4];
#pragma unroll
      for (int mi = 0; mi < 2; ++mi) {
        int rb = wm * 32 + mi * 16;
        a[mi][0] = sA[(rb + g) * 36 + kk * 8 + tg];
        a[mi][1] = sA[(rb + g + 8) * 36 + kk * 8 + tg];
        a[mi][2] = sA[(rb + g) * 36 + kk * 8 + tg + 4];
        a[mi][3] = sA[(rb + g + 8) * 36 + kk * 8 + tg + 4];
      }
#pragma unroll
      for (int ni = 0; ni < 8; ++ni) {
        int rb = wn * 64 + ni * 8 + g;
        uint32_t b0 = sB[rb * 36 + kk * 8 + tg];
        uint32_t b1 = sB[rb * 36 + kk * 8 + tg + 4];
        mma16(acc[0][ni], a[0], b0, b1);
        mma16(acc[1][ni], a[1], b0, b1);
      }
    }
  }

  // ---- epilogue ----
#pragma unroll
  for (int mi = 0; mi < 2; ++mi) {
    int row = m0 + wm * 32 + mi * 16 + g;
#pragma unroll
    for (int ni = 0; ni < 8; ++ni) {
      int col = n0 + wn * 64 + ni * 8 + 2 * tg;
      if (OUT_HALF) {
        uint32_t* Ch = (uint32_t*)Cp;  // half2 view
        Ch[(size_t)row * 256 + (col >> 1)] =
            f2h2(acc[mi][ni][0], acc[mi][ni][1]);
        Ch[(size_t)(row + 8) * 256 + (col >> 1)] =
            f2h2(acc[mi][ni][2], acc[mi][ni][3]);
      } else {
        float* Cf = (float*)Cp;
        *reinterpret_cast<float2*>(Cf + (size_t)row * kD + col) =
            make_float2(acc[mi][ni][0], acc[mi][ni][1]);
        *reinterpret_cast<float2*>(Cf + (size_t)(row + 8) * kD + col) =
            make_float2(acc[mi][ni][2], acc[mi][ni][3]);
      }
    }
  }
}

// ---------------------------------------------------------------------------
// Flash attention, fp16: CTA = (128-query tile, head, batch), 8 warps x 16
// rows. All operands fp16 in SMEM (rows = 32 half2-words + 4 pad).
// P stays in registers (accumulator->A-fragment pack). V B-frags via
// ldmatrix.x4.trans. Double-buffered K/V via cp.async, 1 barrier per chunk.
// SMEM words: sK[2][64*36]@0, sV[2][64*36]@4608, sQ[128*36]@9216,
// bias[2][64]@13824. Total 13952 w = 55808 B.
// ---------------------------------------------------------------------------
constexpr int kOffK = 0;
constexpr int kOffV = 4608;
constexpr int kOffQ = 9216;
constexpr int kOffBias = 13824;
constexpr int kAttnSmem = 13952 * 4;

__global__ void __launch_bounds__(256, 2)
    attn_f16(const __half* __restrict__ Qg, const __half* __restrict__ Kg,
             const __half* __restrict__ Vg, const int* __restrict__ mask,
             __half* __restrict__ Og) {
  extern __shared__ uint32_t asm_[];
  float* sBias = reinterpret_cast<float*>(asm_ + kOffBias);

  const int tid = threadIdx.x;
  const int lane = tid & 31;
  const int w = tid >> 5;
  const int g = lane >> 2;
  const int tg = lane & 3;
  const int bb = blockIdx.z;
  const int h = blockIdx.y;
  const int q0 = blockIdx.x * 128;
  const int colh = h * kDK;
  const size_t qrow0 = (size_t)bb * kT + q0;
  const size_t kvrow0 = (size_t)bb * kT;
  const int w16 = w * 16;

  const uint32_t smem_base = smem_u32(asm_);
  const uint32_t skb = smem_base + kOffK * 4;
  const uint32_t svb = smem_base + kOffV * 4;
  const uint32_t sqb = smem_base + kOffQ * 4;

  // ldmatrix lane constants: matrix m = lane>>3, row r = lane&7
  const int lm_row = ((lane >> 3) & 1) * 8 + (lane & 7);  // key row within 16
  const int lm_col = (lane >> 4) * 4;                     // dni*4 words

  // ---- staging: K/V chunk j into buffer buf (raw fp16 copies) ----
  auto stage_async = [&](int j, int buf) {
#pragma unroll
    for (int it = 0; it < 2; ++it) {
      int task = it * 256 + tid;   // row(6b) x granule(3b)
      int row = task >> 3;
      int gr = task & 7;
      const __half* ks = Kg + (kvrow0 + j * 64 + row) * kD + colh + gr * 8;
      const __half* vs = Vg + (kvrow0 + j * 64 + row) * kD + colh + gr * 8;
      cpa16(skb + (buf * 2304 + row * 36 + gr * 4) * 4, ks);
      cpa16(svb + (buf * 2304 + row * 36 + gr * 4) * 4, vs);
    }
    if (tid < 64)
      sBias[buf * 64 + tid] =
          mask[kvrow0 + j * 64 + tid] ? 0.f : -1.4426950e30f;
    CP_COMMIT();
  };

  // ---- stage Q (128x64) + chunk 0 ----
#pragma unroll
  for (int it = 0; it < 4; ++it) {
    int task = it * 256 + tid;     // row(7b) x granule(3b)
    int row = task >> 3;
    int gr = task & 7;
    cpa16(sqb + (row * 36 + gr * 4) * 4,
          Qg + (qrow0 + row) * kD + colh + gr * 8);
  }
  CP_COMMIT();
  stage_async(0, 0);
  CP_WAIT0();
  __syncthreads();

  // ---- lift Q A-fragments ----
  const uint32_t* sQ = asm_ + kOffQ;
  uint32_t aq[4][4];
#pragma unroll
  for (int kk = 0; kk < 4; ++kk) {
    aq[kk][0] = sQ[(w16 + g) * 36 + kk * 8 + tg];
    aq[kk][1] = sQ[(w16 + g + 8) * 36 + kk * 8 + tg];
    aq[kk][2] = sQ[(w16 + g) * 36 + kk * 8 + tg + 4];
    aq[kk][3] = sQ[(w16 + g + 8) * 36 + kk * 8 + tg + 4];
  }

  float o[8][4];
#pragma unroll
  for (int ni = 0; ni < 8; ++ni)
#pragma unroll
    for (int c = 0; c < 4; ++c) o[ni][c] = 0.f;
  float mrow0 = -INFINITY, mrow1 = -INFINITY;
  float l0 = 0.f, l1 = 0.f;
  const float sc = kSmScale * kLog2e;

  for (int j = 0; j < kT / 64; ++j) {
    const int p = j & 1;
    const uint32_t* sk = asm_ + kOffK + p * 2304;
    const uint32_t svbase = svb + p * 2304 * 4;
    const float* bias = sBias + p * 64;

    // ---- S = Q K^T ----
    float s[8][4];
#pragma unroll
    for (int ni = 0; ni < 8; ++ni)
#pragma unroll
      for (int c = 0; c < 4; ++c) s[ni][c] = 0.f;
#pragma unroll
    for (int kk = 0; kk < 4; ++kk)
#pragma unroll
      for (int ni = 0; ni < 8; ++ni) {
        uint32_t b0 = sk[(ni * 8 + g) * 36 + kk * 8 + tg];
        uint32_t b1 = sk[(ni * 8 + g) * 36 + kk * 8 + tg + 4];
        mma16(s[ni], aq[kk], b0, b1);
      }

    // ---- kick next chunk's staging (overlaps softmax + PV) ----
    if (j + 1 < kT / 64) stage_async(j + 1, 1 - p);

    // ---- scale + mask bias, row max ----
    float mx0 = -INFINITY, mx1 = -INFINITY;
#pragma unroll
    for (int ni = 0; ni < 8; ++ni) {
      float bb0 = bias[ni * 8 + 2 * tg];
      float bb1 = bias[ni * 8 + 2 * tg + 1];
      s[ni][0] = s[ni][0] * sc + bb0;
      s[ni][1] = s[ni][1] * sc + bb1;
      s[ni][2] = s[ni][2] * sc + bb0;
      s[ni][3] = s[ni][3] * sc + bb1;
      mx0 = fmaxf(mx0, fmaxf(s[ni][0], s[ni][1]));
      mx1 = fmaxf(mx1, fmaxf(s[ni][2], s[ni][3]));
    }
    mx0 = fmaxf(mx0, __shfl_xor_sync(0xffffffffu, mx0, 1));
    mx0 = fmaxf(mx0, __shfl_xor_sync(0xffffffffu, mx0, 2));
    mx1 = fmaxf(mx1, __shfl_xor_sync(0xffffffffu, mx1, 1));
    mx1 = fmaxf(mx1, __shfl_xor_sync(0xffffffffu, mx1, 2));
    float mn0 = fmaxf(mrow0, mx0);
    float mn1 = fmaxf(mrow1, mx1);
    float al0 = ex2(mrow0 - mn0);
    float al1 = ex2(mrow1 - mn1);
    mrow0 = mn0;
    mrow1 = mn1;

    // ---- p = exp2(s - mn) in place; row sums ----
    float rs0 = 0.f, rs1 = 0.f;
#pragma unroll
    for (int ni = 0; ni < 8; ++ni) {
      s[ni][0] = ex2(s[ni][0] - mn0);
      s[ni][1] = ex2(s[ni][1] - mn0);
      s[ni][2] = ex2(s[ni][2] - mn1);
      s[ni][3] = ex2(s[ni][3] - mn1);
      rs0 += s[ni][0] + s[ni][1];
      rs1 += s[ni][2] + s[ni][3];
    }
    rs0 += __shfl_xor_sync(0xffffffffu, rs0, 1);
    rs0 += __shfl_xor_sync(0xffffffffu, rs0, 2);
    rs1 += __shfl_xor_sync(0xffffffffu, rs1, 1);
    rs1 += __shfl_xor_sync(0xffffffffu, rs1, 2);
    l0 = l0 * al0 + rs0;
    l1 = l1 * al1 + rs1;
#pragma unroll
    for (int ni = 0; ni < 8; ++ni) {
      o[ni][0] *= al0;
      o[ni][1] *= al0;
      o[ni][2] *= al1;
      o[ni][3] *= al1;
    }

    // ---- O += P V : P packed from registers, V via ldmatrix.trans ----
#pragma unroll
    for (int kkp = 0; kkp < 4; ++kkp) {
      uint32_t pa[4];
      pa[0] = f2h2(s[2 * kkp][0], s[2 * kkp][1]);
      pa[1] = f2h2(s[2 * kkp][2], s[2 * kkp][3]);
      pa[2] = f2h2(s[2 * kkp + 1][0], s[2 * kkp + 1][1]);
      pa[3] = f2h2(s[2 * kkp + 1][2], s[2 * kkp + 1][3]);
#pragma unroll
      for (int nip = 0; nip < 4; ++nip) {
        uint32_t v0, v1, v2, v3;
        uint32_t addr =
            svbase + (((16 * kkp + lm_row) * 36) + nip * 8 + lm_col) * 4;
        ldsm4t(v0, v1, v2, v3, addr);
        mma16(o[2 * nip], pa, v0, v1);
        mma16(o[2 * nip + 1], pa, v2, v3);
      }
    }

    // ---- next chunk's copies done + visible ----
    CP_WAIT0();
    __syncthreads();
  }

  // ---- normalize, store O (fp16) ----
  const float inv0 = 1.f / l0;
  const float inv1 = 1.f / l1;
  uint32_t* Oh = reinterpret_cast<uint32_t*>(Og);  // half2 view
#pragma unroll
  for (int ni = 0; ni < 8; ++ni) {
    size_t idx = (qrow0 + w16 + g) * 256 + ((colh + ni * 8) >> 1) + tg;
    Oh[idx] = f2h2(o[ni][0] * inv0, o[ni][1] * inv0);
    Oh[idx + 8 * 256] = f2h2(o[ni][2] * inv1, o[ni][3] * inv1);
  }
}

// ---------------------------------------------------------------------------
extern "C" void kernel_launch(void* const* d_in, const int* in_sizes, int n_in,
                              void* d_out, int out_size) {
  const float* skel = (const float*)d_in[0];
  const float* sens = (const float*)d_in[1];
  const int* mask_skel = (const int*)d_in[2];
  const int* mask_sens = (const int*)d_in[3];
  const float* Wq_s2e = (const float*)d_in[4];
  const float* Wk_e = (const float*)d_in[5];
  const float* Wv_e = (const float*)d_in[6];
  const float* Wq_e2s = (const float*)d_in[7];
  const float* Wk_s = (const float*)d_in[8];
  const float* Wv_s = (const float*)d_in[9];
  const float* Wo_s = (const float*)d_in[10];
  const float* Wo_e = (const float*)d_in[11];

  float* out_e2s = (float*)d_out;                     // tuple element 0
  float* out_s2e = (float*)d_out + (size_t)kM * kD;   // tuple element 1

  __half *Qp, *Kp, *Vp, *Op;
  cudaGetSymbolAddress((void**)&Qp, g_Q);
  cudaGetSymbolAddress((void**)&Kp, g_K);
  cudaGetSymbolAddress((void**)&Vp, g_V);
  cudaGetSymbolAddress((void**)&Op, g_O);

  cudaFuncSetAttribute(attn_f16, cudaFuncAttributeMaxDynamicSharedMemorySize,
                       kAttnSmem);

  dim3 ggrid(kM / 128, kD / 128);  // 64 x 4
  dim3 agrid(kT / 128, kH, kB);    // 16 x 8 x 4

  // ---- s2e: skel queries attend over sensor K/V ----
  gemm_f16<false, true><<<ggrid, 256>>>(skel, Wq_s2e, Qp);
  gemm_f16<false, true><<<ggrid, 256>>>(sens, Wk_e, Kp);
  gemm_f16<false, true><<<ggrid, 256>>>(sens, Wv_e, Vp);
  attn_f16<<<agrid, 256, kAttnSmem>>>(Qp, Kp, Vp, mask_sens, Op);
  gemm_f16<true, false><<<ggrid, 256>>>(Op, Wo_e, out_s2e);

  // ---- e2s: sensor queries attend over skeleton K/V ----
  gemm_f16<false, true><<<ggrid, 256>>>(sens, Wq_e2s, Qp);
  gemm_f16<false, true><<<ggrid, 256>>>(skel, Wk_s, Kp);
  gemm_f16<false, true><<<ggrid, 256>>>(skel, Wv_s, Vp);
  attn_f16<<<agrid, 256, kAttnSmem>>>(Qp, Kp, Vp, mask_skel, Op);
  gemm_f16<true, false><<<ggrid, 256>>>(Op, Wo_s, out_e2s);
}

// round 7
// speedup vs baseline: 3.3622x; 1.0931x over previous
#include <cuda_runtime.h>
#include <cuda_fp16.h>
#include <cstdint>
#include <cstddef>

// ---------------------------------------------------------------------------
// Dual cross-attention (e2s, s2e), fp16 mma.sync (m16n8k16, fp32 accum).
// R7: one-time fp32->fp16 conversion of activations + weights; all GEMMs pure
// fp16 with cp.async double-buffering and ldmatrix fragment loads; attention
// S-loop K fragments via ldmatrix.x4 (non-trans).
// ---------------------------------------------------------------------------

constexpr int kB = 4;
constexpr int kT = 2048;
constexpr int kD = 512;
constexpr int kH = 8;
constexpr int kDK = 64;
constexpr int kM = kB * kT;  // 8192 rows
constexpr float kSmScale = 1.5f / 8.0f;  // SCALE / sqrt(DK)
constexpr float kLog2e = 1.4426950408889634f;

__device__ __half g_Q[(size_t)kM * kD];
__device__ __half g_K[(size_t)kM * kD];
__device__ __half g_V[(size_t)kM * kD];
__device__ __half g_O[(size_t)kM * kD];
__device__ __half g_Ah[2 * (size_t)kM * kD];     // fp16 skel | sens
__device__ __half g_Wh[8 * (size_t)kD * kD];     // fp16 weights

__device__ __forceinline__ uint32_t f2h2(float lo, float hi) {
  uint32_t r;
  asm("cvt.rn.f16x2.f32 %0, %1, %2;" : "=r"(r) : "f"(hi), "f"(lo));
  return r;
}

__device__ __forceinline__ float ex2(float f) {
  float r;
  asm("ex2.approx.ftz.f32 %0, %1;" : "=f"(r) : "f"(f));
  return r;
}

__device__ __forceinline__ uint32_t smem_u32(const void* p) {
  uint32_t a;
  asm("{ .reg .u64 t; cvta.to.shared.u64 t, %1; cvt.u32.u64 %0, t; }"
      : "=r"(a) : "l"(p));
  return a;
}

__device__ __forceinline__ void cpa16(uint32_t dst, const void* src) {
  asm volatile("cp.async.cg.shared.global [%0], [%1], 16;"
               :: "r"(dst), "l"(src));
}
#define CP_COMMIT() asm volatile("cp.async.commit_group;" ::: "memory")
#define CP_WAIT0() asm volatile("cp.async.wait_group 0;" ::: "memory")

// D += A(16x16) * B(16x8), fp16 in, fp32 accum.
__device__ __forceinline__ void mma16(float* d, const uint32_t* a, uint32_t b0,
                                      uint32_t b1) {
  asm volatile(
      "mma.sync.aligned.m16n8k16.row.col.f32.f16.f16.f32 "
      "{%0,%1,%2,%3}, {%4,%5,%6,%7}, {%8,%9}, {%0,%1,%2,%3};\n"
      : "+f"(d[0]), "+f"(d[1]), "+f"(d[2]), "+f"(d[3])
      : "r"(a[0]), "r"(a[1]), "r"(a[2]), "r"(a[3]), "r"(b0), "r"(b1));
}

__device__ __forceinline__ void ldsm4(uint32_t& r0, uint32_t& r1, uint32_t& r2,
                                      uint32_t& r3, uint32_t addr) {
  asm volatile(
      "ldmatrix.sync.aligned.m8n8.x4.shared.b16 {%0,%1,%2,%3}, [%4];"
      : "=r"(r0), "=r"(r1), "=r"(r2), "=r"(r3) : "r"(addr));
}

__device__ __forceinline__ void ldsm4t(uint32_t& r0, uint32_t& r1,
                                       uint32_t& r2, uint32_t& r3,
                                       uint32_t addr) {
  asm volatile(
      "ldmatrix.sync.aligned.m8n8.x4.trans.shared.b16 {%0,%1,%2,%3}, [%4];"
      : "=r"(r0), "=r"(r1), "=r"(r2), "=r"(r3) : "r"(addr));
}

// ---------------------------------------------------------------------------
// One-time fp32 -> fp16 conversions.
// ---------------------------------------------------------------------------
__global__ void cvt_act(const float* __restrict__ a0,
                        const float* __restrict__ a1, __half* __restrict__ o) {
  const float* src = blockIdx.y ? a1 : a0;
  uint2* dst = reinterpret_cast<uint2*>(o + (size_t)blockIdx.y * kM * kD);
  int idx = blockIdx.x * blockDim.x + threadIdx.x;  // float4 granules
  float4 v = reinterpret_cast<const float4*>(src)[idx];
  dst[idx] = make_uint2(f2h2(v.x, v.y), f2h2(v.z, v.w));
}

__global__ void cvt_w(const float* w0, const float* w1, const float* w2,
                      const float* w3, const float* w4, const float* w5,
                      const float* w6, const float* w7,
                      __half* __restrict__ o) {
  const float* srcs[8] = {w0, w1, w2, w3, w4, w5, w6, w7};
  const float* src = srcs[blockIdx.y];
  uint2* dst = reinterpret_cast<uint2*>(o + (size_t)blockIdx.y * kD * kD);
  int idx = blockIdx.x * blockDim.x + threadIdx.x;
  float4 v = reinterpret_cast<const float4*>(src)[idx];
  dst[idx] = make_uint2(f2h2(v.x, v.y), f2h2(v.z, v.w));
}

// ---------------------------------------------------------------------------
// C[8192,512] = A[8192,512] @ W[512,512]^T, all-fp16 operands.
// CTA 128x128, k-tile 64, 8 warps = 4(M) x 2(N). cp.async double-buffered,
// one barrier per k-tile, ldmatrix.x4 fragments.
// Dynamic smem words: sA[2][128*36]@0, sB[2][128*36]@9216 -> 18432 w.
// ---------------------------------------------------------------------------
constexpr int kGemmSmem = 18432 * 4;

template <bool OUT_HALF>
__global__ void __launch_bounds__(256, 2)
    gemm_h(const __half* __restrict__ A, const __half* __restrict__ W,
           void* __restrict__ Cp) {
  extern __shared__ uint32_t gsm[];

  const int tid = threadIdx.x;
  const int lane = tid & 31;
  const int wid = tid >> 5;
  const int wm = wid & 3;
  const int wn = wid >> 2;
  const int g = lane >> 2;
  const int tg = lane & 3;
  const int m0 = blockIdx.x * 128;
  const int n0 = blockIdx.y * 128;

  const uint32_t sAb = smem_u32(gsm);
  const uint32_t sBb = sAb + 9216 * 4;

  // ldmatrix lane addressing
  const int a_row = ((lane >> 3) & 1) * 8 + (lane & 7);
  const int a_col = (lane >> 4) * 4;  // word offset
  const int b_row = (lane >> 4) * 8 + (lane & 7);
  const int b_col = ((lane >> 3) & 1) * 4;

  float acc[2][8][4];
#pragma unroll
  for (int mi = 0; mi < 2; ++mi)
#pragma unroll
    for (int ni = 0; ni < 8; ++ni)
#pragma unroll
      for (int c = 0; c < 4; ++c) acc[mi][ni][c] = 0.f;

  auto stage = [&](int kt, int buf) {
#pragma unroll
    for (int it = 0; it < 4; ++it) {
      int task = it * 256 + tid;  // row(7b) x granule(3b)
      int row = task >> 3;
      int gr = task & 7;
      cpa16(sAb + (buf * 4608 + row * 36 + gr * 4) * 4,
            A + (size_t)(m0 + row) * kD + kt * 64 + gr * 8);
      cpa16(sBb + (buf * 4608 + row * 36 + gr * 4) * 4,
            W + (size_t)(n0 + row) * kD + kt * 64 + gr * 8);
    }
    CP_COMMIT();
  };

  stage(0, 0);
  CP_WAIT0();
  __syncthreads();

  for (int kt = 0; kt < 8; ++kt) {
    const int p = kt & 1;
    if (kt < 7) stage(kt + 1, 1 - p);  // writes other buffer; overlaps compute
    const uint32_t sAp = sAb + p * 4608 * 4;
    const uint32_t sBp = sBb + p * 4608 * 4;
#pragma unroll
    for (int kk = 0; kk < 4; ++kk) {
      uint32_t a[2][4];
#pragma unroll
      for (int mi = 0; mi < 2; ++mi) {
        uint32_t addr =
            sAp + (((wm * 32 + mi * 16 + a_row) * 36) + kk * 8 + a_col) * 4;
        ldsm4(a[mi][0], a[mi][1], a[mi][2], a[mi][3], addr);
      }
#pragma unroll
      for (int ni2 = 0; ni2 < 4; ++ni2) {
        uint32_t b0, b1, b2, b3;
        uint32_t addr =
            sBp + (((wn * 64 + ni2 * 16 + b_row) * 36) + kk * 8 + b_col) * 4;
        ldsm4(b0, b1, b2, b3, addr);
        mma16(acc[0][2 * ni2], a[0], b0, b1);
        mma16(acc[0][2 * ni2 + 1], a[0], b2, b3);
        mma16(acc[1][2 * ni2], a[1], b0, b1);
        mma16(acc[1][2 * ni2 + 1], a[1], b2, b3);
      }
    }
    CP_WAIT0();
    __syncthreads();
  }

#pragma unroll
  for (int mi = 0; mi < 2; ++mi) {
    int row = m0 + wm * 32 + mi * 16 + g;
#pragma unroll
    for (int ni = 0; ni < 8; ++ni) {
      int col = n0 + wn * 64 + ni * 8 + 2 * tg;
      if (OUT_HALF) {
        uint32_t* Ch = (uint32_t*)Cp;  // half2 view
        Ch[(size_t)row * 256 + (col >> 1)] =
            f2h2(acc[mi][ni][0], acc[mi][ni][1]);
        Ch[(size_t)(row + 8) * 256 + (col >> 1)] =
            f2h2(acc[mi][ni][2], acc[mi][ni][3]);
      } else {
        float* Cf = (float*)Cp;
        *reinterpret_cast<float2*>(Cf + (size_t)row * kD + col) =
            make_float2(acc[mi][ni][0], acc[mi][ni][1]);
        *reinterpret_cast<float2*>(Cf + (size_t)(row + 8) * kD + col) =
            make_float2(acc[mi][ni][2], acc[mi][ni][3]);
      }
    }
  }
}

// ---------------------------------------------------------------------------
// Flash attention, fp16 (R6 structure; K fragments now via ldmatrix.x4).
// SMEM words: sK[2][64*36]@0, sV[2][64*36]@4608, sQ[128*36]@9216,
// bias[2][64]@13824. Total 13952 w = 55808 B.
// ---------------------------------------------------------------------------
constexpr int kOffK = 0;
constexpr int kOffV = 4608;
constexpr int kOffQ = 9216;
constexpr int kOffBias = 13824;
constexpr int kAttnSmem = 13952 * 4;

__global__ void __launch_bounds__(256, 2)
    attn_f16(const __half* __restrict__ Qg, const __half* __restrict__ Kg,
             const __half* __restrict__ Vg, const int* __restrict__ mask,
             __half* __restrict__ Og) {
  extern __shared__ uint32_t asm_[];
  float* sBias = reinterpret_cast<float*>(asm_ + kOffBias);

  const int tid = threadIdx.x;
  const int lane = tid & 31;
  const int w = tid >> 5;
  const int g = lane >> 2;
  const int tg = lane & 3;
  const int bb = blockIdx.z;
  const int h = blockIdx.y;
  const int q0 = blockIdx.x * 128;
  const int colh = h * kDK;
  const size_t qrow0 = (size_t)bb * kT + q0;
  const size_t kvrow0 = (size_t)bb * kT;
  const int w16 = w * 16;

  const uint32_t smem_base = smem_u32(asm_);
  const uint32_t skb = smem_base + kOffK * 4;
  const uint32_t svb = smem_base + kOffV * 4;
  const uint32_t sqb = smem_base + kOffQ * 4;

  // ldmatrix lane constants
  const int kb_row = (lane >> 4) * 8 + (lane & 7);   // non-trans B (K)
  const int kb_col = ((lane >> 3) & 1) * 4;
  const int lm_row = ((lane >> 3) & 1) * 8 + (lane & 7);  // trans (V)
  const int lm_col = (lane >> 4) * 4;

  // ---- staging: K/V chunk j into buffer buf (raw fp16 copies) ----
  auto stage_async = [&](int j, int buf) {
#pragma unroll
    for (int it = 0; it < 2; ++it) {
      int task = it * 256 + tid;  // row(6b) x granule(3b)
      int row = task >> 3;
      int gr = task & 7;
      const __half* ks = Kg + (kvrow0 + j * 64 + row) * kD + colh + gr * 8;
      const __half* vs = Vg + (kvrow0 + j * 64 + row) * kD + colh + gr * 8;
      cpa16(skb + (buf * 2304 + row * 36 + gr * 4) * 4, ks);
      cpa16(svb + (buf * 2304 + row * 36 + gr * 4) * 4, vs);
    }
    if (tid < 64)
      sBias[buf * 64 + tid] =
          mask[kvrow0 + j * 64 + tid] ? 0.f : -1.4426950e30f;
    CP_COMMIT();
  };

  // ---- stage Q (128x64) + chunk 0 ----
#pragma unroll
  for (int it = 0; it < 4; ++it) {
    int task = it * 256 + tid;
    int row = task >> 3;
    int gr = task & 7;
    cpa16(sqb + (row * 36 + gr * 4) * 4,
          Qg + (qrow0 + row) * kD + colh + gr * 8);
  }
  CP_COMMIT();
  stage_async(0, 0);
  CP_WAIT0();
  __syncthreads();

  // ---- lift Q A-fragments ----
  const uint32_t* sQ = asm_ + kOffQ;
  uint32_t aq[4][4];
#pragma unroll
  for (int kk = 0; kk < 4; ++kk) {
    aq[kk][0] = sQ[(w16 + g) * 36 + kk * 8 + tg];
    aq[kk][1] = sQ[(w16 + g + 8) * 36 + kk * 8 + tg];
    aq[kk][2] = sQ[(w16 + g) * 36 + kk * 8 + tg + 4];
    aq[kk][3] = sQ[(w16 + g + 8) * 36 + kk * 8 + tg + 4];
  }

  float o[8][4];
#pragma unroll
  for (int ni = 0; ni < 8; ++ni)
#pragma unroll
    for (int c = 0; c < 4; ++c) o[ni][c] = 0.f;
  float mrow0 = -INFINITY, mrow1 = -INFINITY;
  float l0 = 0.f, l1 = 0.f;
  const float sc = kSmScale * kLog2e;

  for (int j = 0; j < kT / 64; ++j) {
    const int p = j & 1;
    const uint32_t skbase = skb + p * 2304 * 4;
    const uint32_t svbase = svb + p * 2304 * 4;
    const float* bias = sBias + p * 64;

    // ---- S = Q K^T (K B-frags via ldmatrix.x4 non-trans) ----
    float s[8][4];
#pragma unroll
    for (int ni = 0; ni < 8; ++ni)
#pragma unroll
      for (int c = 0; c < 4; ++c) s[ni][c] = 0.f;
#pragma unroll
    for (int kk = 0; kk < 4; ++kk)
#pragma unroll
      for (int ni2 = 0; ni2 < 4; ++ni2) {
        uint32_t b0, b1, b2, b3;
        uint32_t addr =
            skbase + (((ni2 * 16 + kb_row) * 36) + kk * 8 + kb_col) * 4;
        ldsm4(b0, b1, b2, b3, addr);
        mma16(s[2 * ni2], aq[kk], b0, b1);
        mma16(s[2 * ni2 + 1], aq[kk], b2, b3);
      }

    // ---- kick next chunk's staging (overlaps softmax + PV) ----
    if (j + 1 < kT / 64) stage_async(j + 1, 1 - p);

    // ---- scale + mask bias, row max ----
    float mx0 = -INFINITY, mx1 = -INFINITY;
#pragma unroll
    for (int ni = 0; ni < 8; ++ni) {
      float bb0 = bias[ni * 8 + 2 * tg];
      float bb1 = bias[ni * 8 + 2 * tg + 1];
      s[ni][0] = s[ni][0] * sc + bb0;
      s[ni][1] = s[ni][1] * sc + bb1;
      s[ni][2] = s[ni][2] * sc + bb0;
      s[ni][3] = s[ni][3] * sc + bb1;
      mx0 = fmaxf(mx0, fmaxf(s[ni][0], s[ni][1]));
      mx1 = fmaxf(mx1, fmaxf(s[ni][2], s[ni][3]));
    }
    mx0 = fmaxf(mx0, __shfl_xor_sync(0xffffffffu, mx0, 1));
    mx0 = fmaxf(mx0, __shfl_xor_sync(0xffffffffu, mx0, 2));
    mx1 = fmaxf(mx1, __shfl_xor_sync(0xffffffffu, mx1, 1));
    mx1 = fmaxf(mx1, __shfl_xor_sync(0xffffffffu, mx1, 2));
    float mn0 = fmaxf(mrow0, mx0);
    float mn1 = fmaxf(mrow1, mx1);
    float al0 = ex2(mrow0 - mn0);
    float al1 = ex2(mrow1 - mn1);
    mrow0 = mn0;
    mrow1 = mn1;

    // ---- p = exp2(s - mn) in place; row sums ----
    float rs0 = 0.f, rs1 = 0.f;
#pragma unroll
    for (int ni = 0; ni < 8; ++ni) {
      s[ni][0] = ex2(s[ni][0] - mn0);
      s[ni][1] = ex2(s[ni][1] - mn0);
      s[ni][2] = ex2(s[ni][2] - mn1);
      s[ni][3] = ex2(s[ni][3] - mn1);
      rs0 += s[ni][0] + s[ni][1];
      rs1 += s[ni][2] + s[ni][3];
    }
    rs0 += __shfl_xor_sync(0xffffffffu, rs0, 1);
    rs0 += __shfl_xor_sync(0xffffffffu, rs0, 2);
    rs1 += __shfl_xor_sync(0xffffffffu, rs1, 1);
    rs1 += __shfl_xor_sync(0xffffffffu, rs1, 2);
    l0 = l0 * al0 + rs0;
    l1 = l1 * al1 + rs1;
#pragma unroll
    for (int ni = 0; ni < 8; ++ni) {
      o[ni][0] *= al0;
      o[ni][1] *= al0;
      o[ni][2] *= al1;
      o[ni][3] *= al1;
    }

    // ---- O += P V : P packed from registers, V via ldmatrix.trans ----
#pragma unroll
    for (int kkp = 0; kkp < 4; ++kkp) {
      uint32_t pa[4];
      pa[0] = f2h2(s[2 * kkp][0], s[2 * kkp][1]);
      pa[1] = f2h2(s[2 * kkp][2], s[2 * kkp][3]);
      pa[2] = f2h2(s[2 * kkp + 1][0], s[2 * kkp + 1][1]);
      pa[3] = f2h2(s[2 * kkp + 1][2], s[2 * kkp + 1][3]);
#pragma unroll
      for (int nip = 0; nip < 4; ++nip) {
        uint32_t v0, v1, v2, v3;
        uint32_t addr =
            svbase + (((16 * kkp + lm_row) * 36) + nip * 8 + lm_col) * 4;
        ldsm4t(v0, v1, v2, v3, addr);
        mma16(o[2 * nip], pa, v0, v1);
        mma16(o[2 * nip + 1], pa, v2, v3);
      }
    }

    // ---- next chunk's copies done + visible ----
    CP_WAIT0();
    __syncthreads();
  }

  // ---- normalize, store O (fp16) ----
  const float inv0 = 1.f / l0;
  const float inv1 = 1.f / l1;
  uint32_t* Oh = reinterpret_cast<uint32_t*>(Og);  // half2 view
#pragma unroll
  for (int ni = 0; ni < 8; ++ni) {
    size_t idx = (qrow0 + w16 + g) * 256 + ((colh + ni * 8) >> 1) + tg;
    Oh[idx] = f2h2(o[ni][0] * inv0, o[ni][1] * inv0);
    Oh[idx + 8 * 256] = f2h2(o[ni][2] * inv1, o[ni][3] * inv1);
  }
}

// ---------------------------------------------------------------------------
extern "C" void kernel_launch(void* const* d_in, const int* in_sizes, int n_in,
                              void* d_out, int out_size) {
  const float* skel = (const float*)d_in[0];
  const float* sens = (const float*)d_in[1];
  const int* mask_skel = (const int*)d_in[2];
  const int* mask_sens = (const int*)d_in[3];
  const float* Wq_s2e = (const float*)d_in[4];
  const float* Wk_e = (const float*)d_in[5];
  const float* Wv_e = (const float*)d_in[6];
  const float* Wq_e2s = (const float*)d_in[7];
  const float* Wk_s = (const float*)d_in[8];
  const float* Wv_s = (const float*)d_in[9];
  const float* Wo_s = (const float*)d_in[10];
  const float* Wo_e = (const float*)d_in[11];

  float* out_e2s = (float*)d_out;                     // tuple element 0
  float* out_s2e = (float*)d_out + (size_t)kM * kD;   // tuple element 1

  __half *Qp, *Kp, *Vp, *Op, *Ah, *Wh;
  cudaGetSymbolAddress((void**)&Qp, g_Q);
  cudaGetSymbolAddress((void**)&Kp, g_K);
  cudaGetSymbolAddress((void**)&Vp, g_V);
  cudaGetSymbolAddress((void**)&Op, g_O);
  cudaGetSymbolAddress((void**)&Ah, g_Ah);
  cudaGetSymbolAddress((void**)&Wh, g_Wh);

  cudaFuncSetAttribute(attn_f16, cudaFuncAttributeMaxDynamicSharedMemorySize,
                       kAttnSmem);
  cudaFuncSetAttribute(gemm_h<true>,
                       cudaFuncAttributeMaxDynamicSharedMemorySize, kGemmSmem);
  cudaFuncSetAttribute(gemm_h<false>,
                       cudaFuncAttributeMaxDynamicSharedMemorySize, kGemmSmem);

  const __half* skel_h = Ah;
  const __half* sens_h = Ah + (size_t)kM * kD;
  auto Wp = [&](int i) { return (const __half*)(Wh + (size_t)i * kD * kD); };
  // order: 0 Wq_s2e, 1 Wk_e, 2 Wv_e, 3 Wq_e2s, 4 Wk_s, 5 Wv_s, 6 Wo_s, 7 Wo_e

  // ---- one-time conversions ----
  cvt_act<<<dim3(kM * kD / 4 / 256, 2), 256>>>(skel, sens, Ah);
  cvt_w<<<dim3(kD * kD / 4 / 256, 8), 256>>>(Wq_s2e, Wk_e, Wv_e, Wq_e2s, Wk_s,
                                             Wv_s, Wo_s, Wo_e, Wh);

  dim3 ggrid(kM / 128, kD / 128);  // 64 x 4
  dim3 agrid(kT / 128, kH, kB);    // 16 x 8 x 4

  // ---- s2e: skel queries attend over sensor K/V ----
  gemm_h<true><<<ggrid, 256, kGemmSmem>>>(skel_h, Wp(0), Qp);
  gemm_h<true><<<ggrid, 256, kGemmSmem>>>(sens_h, Wp(1), Kp);
  gemm_h<true><<<ggrid, 256, kGemmSmem>>>(sens_h, Wp(2), Vp);
  attn_f16<<<agrid, 256, kAttnSmem>>>(Qp, Kp, Vp, mask_sens, Op);
  gemm_h<false><<<ggrid, 256, kGemmSmem>>>(Op, Wp(7), out_s2e);

  // ---- e2s: sensor queries attend over skeleton K/V ----
  gemm_h<true><<<ggrid, 256, kGemmSmem>>>(sens_h, Wp(3), Qp);
  gemm_h<true><<<ggrid, 256, kGemmSmem>>>(skel_h, Wp(4), Kp);
  gemm_h<true><<<ggrid, 256, kGemmSmem>>>(skel_h, Wp(5), Vp);
  attn_f16<<<agrid, 256, kAttnSmem>>>(Qp, Kp, Vp, mask_skel, Op);
  gemm_h<false><<<ggrid, 256, kGemmSmem>>>(Op, Wp(6), out_e2s);
}